// round 1
// baseline (speedup 1.0000x reference)
#include <cuda_runtime.h>
#include <math.h>

// ---------------- problem constants (hardcoded from reference) ----------------
// B=2, T=8, H=16, W=16, E=512, n_heads=16, head_dim=32, S=4096, L2=512, WINDOW=4
// frames BT = 16, padded frames per batch TPAD = 11

// ---------------- device scratch (no allocation allowed) ----------------
__device__ __align__(128) float g_qkv[8192ull * 1536];        // 50.3 MB
__device__ __align__(128) float g_q  [16ull * 512 * 512];     // roped q (frame,l,E)
__device__ __align__(128) float g_k  [16ull * 512 * 512];     // roped k (frame,l,E)
__device__ __align__(128) float g_v  [16ull * 512 * 512];     // v (frame,l,E)
__device__ __align__(128) float g_qh [16ull * 512 * 512];     // second-proj q
__device__ __align__(128) float g_o  [16ull * 512 * 512];     // attention output
__device__ __align__(128) float g_kp [2ull * 11 * 512 * 512]; // padded proj k
__device__ __align__(128) float g_vp [2ull * 11 * 512 * 512]; // padded proj v
__device__ __align__(128) float g_teK[4 * 512];               // temporal_embed @ Wk^T

// ---------------- generic fp32 GEMM: C[M,N] = A[M,K] @ Wt[N,K]^T + bias ----------------
// 64x64 tile, BK=16, 256 threads, 4x4 per thread.
// pad_remap: out_row = r + (r/4096 + 1)*1536  (insert 3 pad frames per batch)
__global__ void gemm_nt(const float* __restrict__ A, const float* __restrict__ Wt,
                        const float* __restrict__ bias, float* __restrict__ C,
                        int N, int K, int pad_remap)
{
    __shared__ float As[16][68];
    __shared__ float Bs[16][68];
    const int tid = threadIdx.x;
    const int tx = tid & 15, ty = tid >> 4;
    const int m0 = blockIdx.y * 64, n0 = blockIdx.x * 64;
    const int lr = tid >> 2, lc = (tid & 3) << 2;
    const float* Ap = A + (size_t)(m0 + lr) * K + lc;
    const float* Bp = Wt + (size_t)(n0 + lr) * K + lc;

    float acc[4][4] = {};
    for (int k0 = 0; k0 < K; k0 += 16) {
        float4 av = *(const float4*)(Ap + k0);
        float4 bv = *(const float4*)(Bp + k0);
        As[lc + 0][lr] = av.x; As[lc + 1][lr] = av.y;
        As[lc + 2][lr] = av.z; As[lc + 3][lr] = av.w;
        Bs[lc + 0][lr] = bv.x; Bs[lc + 1][lr] = bv.y;
        Bs[lc + 2][lr] = bv.z; Bs[lc + 3][lr] = bv.w;
        __syncthreads();
        #pragma unroll
        for (int k = 0; k < 16; k++) {
            float a[4], b[4];
            *(float4*)a = *(const float4*)&As[k][ty << 2];
            *(float4*)b = *(const float4*)&Bs[k][tx << 2];
            #pragma unroll
            for (int i = 0; i < 4; i++)
                #pragma unroll
                for (int j = 0; j < 4; j++)
                    acc[i][j] += a[i] * b[j];
        }
        __syncthreads();
    }

    float4 bb = *(const float4*)(bias + n0 + (tx << 2));
    #pragma unroll
    for (int i = 0; i < 4; i++) {
        int r = m0 + (ty << 2) + i;
        int out_r = pad_remap ? (r + ((r >> 12) + 1) * 1536) : r;
        float4 res = make_float4(acc[i][0] + bb.x, acc[i][1] + bb.y,
                                 acc[i][2] + bb.z, acc[i][3] + bb.w);
        *(float4*)(C + (size_t)out_r * N + n0 + (tx << 2)) = res;
    }
}

// ---------------- RoPE + stream reorder ----------------
// grid: 8192 tokens (b,s). block: 256 threads, one element-pair each.
// q/k: stream1 (s<2048): frame t=s>>8, l=s&255, 1D rope over pos=l.
//      stream2: frame t=(s-2048)>>8, pos=(s-2048)&255, l=256+pos, 2D rope over (h,w).
// v:   straight reshape: frame t=s>>9, l=s&511, no rope.
__global__ void rope_reorder(const float* __restrict__ qkv)
{
    int token = blockIdx.x;            // b*4096 + s
    int b = token >> 12;
    int s = token & 4095;
    int p = threadIdx.x;               // pair index 0..255 over E
    int j = p & 15;                    // pair index within head (d=32 -> 16 pairs)

    int tqk, lqk, fidx;
    float pos;
    if (s < 2048) {
        tqk = s >> 8; lqk = s & 255;
        fidx = j; pos = (float)lqk;
    } else {
        int s2 = s - 2048;
        tqk = s2 >> 8;
        int pp = s2 & 255;
        lqk = 256 + pp;
        int h = pp >> 4, w = pp & 15;
        if (j < 8) { fidx = 2 * j;            pos = (float)h; }
        else       { fidx = 2 * (j - 8) + 1;  pos = (float)w; }
    }
    float freq = powf(10000.0f, -(float)fidx * (1.0f / 16.0f));
    float ang = pos * freq;
    float sn, cs;
    sincosf(ang, &sn, &cs);

    const float* row = qkv + (size_t)token * 1536;
    int frame = b * 8 + tqk;
    size_t ob = ((size_t)frame * 512 + lqk) * 512 + 2 * p;

    float2 qv = *(const float2*)(row + 2 * p);
    g_q[ob]     = qv.x * cs - qv.y * sn;
    g_q[ob + 1] = qv.x * sn + qv.y * cs;

    float2 kv = *(const float2*)(row + 512 + 2 * p);
    g_k[ob]     = kv.x * cs - kv.y * sn;
    g_k[ob + 1] = kv.x * sn + kv.y * cs;

    // v: different frame mapping
    float2 vv = *(const float2*)(row + 1024 + 2 * p);
    size_t vb = ((size_t)(b * 8 + (s >> 9)) * 512 + (s & 511)) * 512 + 2 * p;
    g_v[vb]     = vv.x;
    g_v[vb + 1] = vv.y;
}

// ---------------- fill the 3 leading pad frames of kproj/vproj with biases ----------------
__global__ void fill_pad(const float* __restrict__ bias)
{
    int idx = blockIdx.x * 256 + threadIdx.x;   // over 2*3*512*512 elements
    int e = idx & 511;
    int rl = idx >> 9;                          // b*1536 + tp*512 + l
    int b = rl / 1536;
    int rem = rl - b * 1536;
    size_t o = ((size_t)b * 11 * 512 + rem) * 512 + e;
    g_kp[o] = bias[512 + e];
    g_vp[o] = bias[1024 + e];
}

// ---------------- teK[i][e] = temporal_embed[i] . Wk[e] ----------------
__global__ void compute_teK(const float* __restrict__ te, const float* __restrict__ W)
{
    int i = blockIdx.y;
    int e = blockIdx.x * 64 + threadIdx.x;
    const float* wk = W + (size_t)(512 + e) * 512;
    const float* tr = te + i * 512;
    float sacc = 0.f;
    for (int k = 0; k < 512; k++) sacc += tr[k] * wk[k];
    g_teK[i * 512 + e] = sacc;
}

// ---------------- flash attention ----------------
// grid (4 qtiles, 16 heads, 16 frames), 128 threads; one q-row per thread.
// keys: 2048 = 4 window slots x 512; slot i reads padded frame (b*11 + t + i),
// key vec = kproj + teK[i]. Value = vproj.
__global__ void attn_kernel()
{
    int f = blockIdx.z, n = blockIdx.y;
    int row = blockIdx.x * 128 + threadIdx.x;
    int b = f >> 3, t = f & 7;

    __shared__ float Ks[64 * 32];
    __shared__ float Vs[64 * 32];

    const float scale = 0.17677669529663689f;  // 1/sqrt(32)
    float q[32], o[32];
    const float* qp = g_qh + ((size_t)f * 512 + row) * 512 + n * 32;
    #pragma unroll
    for (int j4 = 0; j4 < 8; j4++) {
        float4 v = *(const float4*)(qp + j4 * 4);
        q[j4*4+0] = v.x * scale; q[j4*4+1] = v.y * scale;
        q[j4*4+2] = v.z * scale; q[j4*4+3] = v.w * scale;
    }
    #pragma unroll
    for (int j = 0; j < 32; j++) o[j] = 0.f;
    float m = -1e30f, lsum = 0.f;

    for (int cc = 0; cc < 32; cc++) {
        int i = cc >> 3;
        int lbase = (cc & 7) * 64;
        size_t fr = (size_t)(b * 11 + t + i);
        const float* kbase = g_kp + (fr * 512 + lbase) * 512 + n * 32;
        const float* vbase = g_vp + (fr * 512 + lbase) * 512 + n * 32;
        const float* tek   = g_teK + i * 512 + n * 32;

        __syncthreads();
        #pragma unroll
        for (int u = 0; u < 4; u++) {
            int pidx = threadIdx.x + u * 128;     // 0..511
            int l = pidx >> 3, d4 = pidx & 7;
            float4 kv = *(const float4*)(kbase + (size_t)l * 512 + d4 * 4);
            float4 tv = *(const float4*)(tek + d4 * 4);
            kv.x += tv.x; kv.y += tv.y; kv.z += tv.z; kv.w += tv.w;
            *(float4*)&Ks[pidx * 4] = kv;
            *(float4*)&Vs[pidx * 4] = *(const float4*)(vbase + (size_t)l * 512 + d4 * 4);
        }
        __syncthreads();

        for (int kk = 0; kk < 64; kk++) {
            const float* kp = Ks + kk * 32;
            float s = 0.f;
            #pragma unroll
            for (int j = 0; j < 32; j++) s += q[j] * kp[j];
            const float* vp = Vs + kk * 32;
            if (s <= m) {
                float pw = __expf(s - m);
                lsum += pw;
                #pragma unroll
                for (int j = 0; j < 32; j++) o[j] += pw * vp[j];
            } else {
                float corr = __expf(m - s);
                m = s;
                lsum = lsum * corr + 1.f;
                #pragma unroll
                for (int j = 0; j < 32; j++) o[j] = o[j] * corr + vp[j];
            }
        }
    }

    float inv = 1.f / lsum;
    float* op = g_o + ((size_t)f * 512 + row) * 512 + n * 32;
    #pragma unroll
    for (int j4 = 0; j4 < 8; j4++) {
        float4 v = make_float4(o[j4*4+0]*inv, o[j4*4+1]*inv, o[j4*4+2]*inv, o[j4*4+3]*inv);
        *(float4*)(op + j4 * 4) = v;
    }
}

// ---------------- launcher ----------------
extern "C" void kernel_launch(void* const* d_in, const int* in_sizes, int n_in,
                              void* d_out, int out_size)
{
    const float* hidden = (const float*)d_in[0];   // (2,4096,512)
    const float* W      = (const float*)d_in[1];   // (1536,512)
    const float* bias   = (const float*)d_in[2];   // (1536)
    const float* Wo     = (const float*)d_in[3];   // (512,512)
    const float* bo     = (const float*)d_in[4];   // (512)
    const float* te     = (const float*)d_in[5];   // (4,512)
    float* out = (float*)d_out;

    float *p_qkv, *p_q, *p_k, *p_v, *p_qh, *p_o, *p_kp, *p_vp;
    cudaGetSymbolAddress((void**)&p_qkv, g_qkv);
    cudaGetSymbolAddress((void**)&p_q,   g_q);
    cudaGetSymbolAddress((void**)&p_k,   g_k);
    cudaGetSymbolAddress((void**)&p_v,   g_v);
    cudaGetSymbolAddress((void**)&p_qh,  g_qh);
    cudaGetSymbolAddress((void**)&p_o,   g_o);
    cudaGetSymbolAddress((void**)&p_kp,  g_kp);
    cudaGetSymbolAddress((void**)&p_vp,  g_vp);

    // 1) qkv = hidden @ in_proj_W^T + b   (8192 x 1536, K=512)
    gemm_nt<<<dim3(1536 / 64, 8192 / 64), 256>>>(hidden, W, bias, p_qkv, 1536, 512, 0);

    // 2) RoPE + stream reorder into g_q/g_k/g_v
    rope_reorder<<<8192, 256>>>(p_qkv);

    // 3) pad frames of kproj/vproj = bias (projected zero rows)
    fill_pad<<<(2 * 3 * 512 * 512) / 256, 256>>>(bias);

    // 4) teK = temporal_embed @ Wk^T
    compute_teK<<<dim3(8, 4), 64>>>(te, W);

    // 5) qh = q_mha @ Wq^T + bq
    gemm_nt<<<dim3(8, 128), 256>>>(p_q, W, bias, p_qh, 512, 512, 0);
    // 6) kproj (padded) = k_comb @ Wk^T + bk
    gemm_nt<<<dim3(8, 128), 256>>>(p_k, W + 512 * 512, bias + 512, p_kp, 512, 512, 1);
    // 7) vproj (padded) = v_comb @ Wv^T + bv
    gemm_nt<<<dim3(8, 128), 256>>>(p_v, W + 1024 * 512, bias + 1024, p_vp, 512, 512, 1);

    // 8) sliding-window attention
    attn_kernel<<<dim3(4, 16, 16), 128>>>();

    // 9) out = o @ Wo^T + bo  (row order == d_out layout)
    gemm_nt<<<dim3(8, 128), 256>>>(p_o, Wo, bo, out, 512, 512, 0);
}

// round 2
// speedup vs baseline: 1.0221x; 1.0221x over previous
#include <cuda_runtime.h>
#include <math.h>

// ---------------- problem constants (hardcoded from reference) ----------------
// B=2, T=8, H=16, W=16, E=512, n_heads=16, head_dim=32, S=4096, L2=512, WINDOW=4
// frames BT = 16, padded frames per batch TPAD = 11

// ---------------- device scratch (no allocation allowed) ----------------
__device__ __align__(128) float g_qkv[8192ull * 1536];        // 50.3 MB
__device__ __align__(128) float g_q  [16ull * 512 * 512];     // roped q (frame,l,E)
__device__ __align__(128) float g_k  [16ull * 512 * 512];     // roped k (frame,l,E)
__device__ __align__(128) float g_v  [16ull * 512 * 512];     // v (frame,l,E)
__device__ __align__(128) float g_qh [16ull * 512 * 512];     // second-proj q
__device__ __align__(128) float g_o  [16ull * 512 * 512];     // attention output
__device__ __align__(128) float g_kp [2ull * 11 * 512 * 512]; // padded proj k
__device__ __align__(128) float g_vp [2ull * 11 * 512 * 512]; // padded proj v
__device__ __align__(128) float g_teK[4 * 512];               // temporal_embed @ Wk^T

// ---------------- generic fp32 GEMM: C[M,N] = A[M,K] @ Wt[N,K]^T + bias ----------------
// 64x64 tile, BK=16, 256 threads, 4x4 per thread.
// pad_remap: out_row = r + (r/4096 + 1)*1536  (insert 3 pad frames per batch)
__global__ void gemm_nt(const float* __restrict__ A, const float* __restrict__ Wt,
                        const float* __restrict__ bias, float* __restrict__ C,
                        int N, int K, int pad_remap)
{
    __shared__ float As[16][68];
    __shared__ float Bs[16][68];
    const int tid = threadIdx.x;
    const int tx = tid & 15, ty = tid >> 4;
    const int m0 = blockIdx.y * 64, n0 = blockIdx.x * 64;
    const int lr = tid >> 2, lc = (tid & 3) << 2;
    const float* Ap = A + (size_t)(m0 + lr) * K + lc;
    const float* Bp = Wt + (size_t)(n0 + lr) * K + lc;

    float acc[4][4] = {};
    for (int k0 = 0; k0 < K; k0 += 16) {
        float4 av = *(const float4*)(Ap + k0);
        float4 bv = *(const float4*)(Bp + k0);
        As[lc + 0][lr] = av.x; As[lc + 1][lr] = av.y;
        As[lc + 2][lr] = av.z; As[lc + 3][lr] = av.w;
        Bs[lc + 0][lr] = bv.x; Bs[lc + 1][lr] = bv.y;
        Bs[lc + 2][lr] = bv.z; Bs[lc + 3][lr] = bv.w;
        __syncthreads();
        #pragma unroll
        for (int k = 0; k < 16; k++) {
            float a[4], b[4];
            *(float4*)a = *(const float4*)&As[k][ty << 2];
            *(float4*)b = *(const float4*)&Bs[k][tx << 2];
            #pragma unroll
            for (int i = 0; i < 4; i++)
                #pragma unroll
                for (int j = 0; j < 4; j++)
                    acc[i][j] += a[i] * b[j];
        }
        __syncthreads();
    }

    float4 bb = *(const float4*)(bias + n0 + (tx << 2));
    #pragma unroll
    for (int i = 0; i < 4; i++) {
        int r = m0 + (ty << 2) + i;
        int out_r = pad_remap ? (r + ((r >> 12) + 1) * 1536) : r;
        float4 res = make_float4(acc[i][0] + bb.x, acc[i][1] + bb.y,
                                 acc[i][2] + bb.z, acc[i][3] + bb.w);
        *(float4*)(C + (size_t)out_r * N + n0 + (tx << 2)) = res;
    }
}

// ---------------- RoPE + stream reorder ----------------
// grid: 8192 tokens (b,s). block: 256 threads, one element-pair each.
// q/k: stream1 (s<2048): frame t=s>>8, l=s&255, 1D rope over pos=l.
//      stream2: frame t=(s-2048)>>8, pos=(s-2048)&255, l=256+pos, 2D rope over (h,w).
// v:   straight reshape: frame t=s>>9, l=s&511, no rope.
__global__ void rope_reorder(const float* __restrict__ qkv)
{
    int token = blockIdx.x;            // b*4096 + s
    int b = token >> 12;
    int s = token & 4095;
    int p = threadIdx.x;               // pair index 0..255 over E
    int j = p & 15;                    // pair index within head (d=32 -> 16 pairs)

    int tqk, lqk, fidx;
    float pos;
    if (s < 2048) {
        tqk = s >> 8; lqk = s & 255;
        fidx = j; pos = (float)lqk;
    } else {
        int s2 = s - 2048;
        tqk = s2 >> 8;
        int pp = s2 & 255;
        lqk = 256 + pp;
        int h = pp >> 4, w = pp & 15;
        if (j < 8) { fidx = 2 * j;            pos = (float)h; }
        else       { fidx = 2 * (j - 8) + 1;  pos = (float)w; }
    }
    float freq = powf(10000.0f, -(float)fidx * (1.0f / 16.0f));
    float ang = pos * freq;
    float sn, cs;
    sincosf(ang, &sn, &cs);

    const float* row = qkv + (size_t)token * 1536;
    int frame = b * 8 + tqk;
    size_t ob = ((size_t)frame * 512 + lqk) * 512 + 2 * p;

    float2 qv = *(const float2*)(row + 2 * p);
    g_q[ob]     = qv.x * cs - qv.y * sn;
    g_q[ob + 1] = qv.x * sn + qv.y * cs;

    float2 kv = *(const float2*)(row + 512 + 2 * p);
    g_k[ob]     = kv.x * cs - kv.y * sn;
    g_k[ob + 1] = kv.x * sn + kv.y * cs;

    // v: different frame mapping
    float2 vv = *(const float2*)(row + 1024 + 2 * p);
    size_t vb = ((size_t)(b * 8 + (s >> 9)) * 512 + (s & 511)) * 512 + 2 * p;
    g_v[vb]     = vv.x;
    g_v[vb + 1] = vv.y;
}

// ---------------- fill the 3 leading pad frames of kproj/vproj with biases ----------------
__global__ void fill_pad(const float* __restrict__ bias)
{
    int idx = blockIdx.x * 256 + threadIdx.x;   // over 2*3*512*512 elements
    int e = idx & 511;
    int rl = idx >> 9;                          // b*1536 + tp*512 + l
    int b = rl / 1536;
    int rem = rl - b * 1536;
    size_t o = ((size_t)b * 11 * 512 + rem) * 512 + e;
    g_kp[o] = bias[512 + e];
    g_vp[o] = bias[1024 + e];
}

// ---------------- teK[i][e] = temporal_embed[i] . Wk[e] ----------------
__global__ void compute_teK(const float* __restrict__ te, const float* __restrict__ W)
{
    int i = blockIdx.y;
    int e = blockIdx.x * 64 + threadIdx.x;
    const float* wk = W + (size_t)(512 + e) * 512;
    const float* tr = te + i * 512;
    float sacc = 0.f;
    for (int k = 0; k < 512; k++) sacc += tr[k] * wk[k];
    g_teK[i * 512 + e] = sacc;
}

// ---------------- flash attention ----------------
// grid (4 qtiles, 16 heads, 16 frames), 128 threads; one q-row per thread.
// keys: 2048 = 4 window slots x 512; slot i reads padded frame (b*11 + t + i),
// key vec = kproj + teK[i]. Value = vproj.
__global__ void attn_kernel()
{
    int f = blockIdx.z, n = blockIdx.y;
    int row = blockIdx.x * 128 + threadIdx.x;
    int b = f >> 3, t = f & 7;

    __shared__ float Ks[64 * 32];
    __shared__ float Vs[64 * 32];

    const float scale = 0.17677669529663689f;  // 1/sqrt(32)
    float q[32], o[32];
    const float* qp = g_qh + ((size_t)f * 512 + row) * 512 + n * 32;
    #pragma unroll
    for (int j4 = 0; j4 < 8; j4++) {
        float4 v = *(const float4*)(qp + j4 * 4);
        q[j4*4+0] = v.x * scale; q[j4*4+1] = v.y * scale;
        q[j4*4+2] = v.z * scale; q[j4*4+3] = v.w * scale;
    }
    #pragma unroll
    for (int j = 0; j < 32; j++) o[j] = 0.f;
    float m = -1e30f, lsum = 0.f;

    for (int cc = 0; cc < 32; cc++) {
        int i = cc >> 3;
        int lbase = (cc & 7) * 64;
        size_t fr = (size_t)(b * 11 + t + i);
        const float* kbase = g_kp + (fr * 512 + lbase) * 512 + n * 32;
        const float* vbase = g_vp + (fr * 512 + lbase) * 512 + n * 32;
        const float* tek   = g_teK + i * 512 + n * 32;

        __syncthreads();
        #pragma unroll
        for (int u = 0; u < 4; u++) {
            int pidx = threadIdx.x + u * 128;     // 0..511
            int l = pidx >> 3, d4 = pidx & 7;
            float4 kv = *(const float4*)(kbase + (size_t)l * 512 + d4 * 4);
            float4 tv = *(const float4*)(tek + d4 * 4);
            kv.x += tv.x; kv.y += tv.y; kv.z += tv.z; kv.w += tv.w;
            *(float4*)&Ks[pidx * 4] = kv;
            *(float4*)&Vs[pidx * 4] = *(const float4*)(vbase + (size_t)l * 512 + d4 * 4);
        }
        __syncthreads();

        for (int kk = 0; kk < 64; kk++) {
            const float* kp = Ks + kk * 32;
            float s = 0.f;
            #pragma unroll
            for (int j = 0; j < 32; j++) s += q[j] * kp[j];
            const float* vp = Vs + kk * 32;
            if (s <= m) {
                float pw = __expf(s - m);
                lsum += pw;
                #pragma unroll
                for (int j = 0; j < 32; j++) o[j] += pw * vp[j];
            } else {
                float corr = __expf(m - s);
                m = s;
                lsum = lsum * corr + 1.f;
                #pragma unroll
                for (int j = 0; j < 32; j++) o[j] = o[j] * corr + vp[j];
            }
        }
    }

    float inv = 1.f / lsum;
    float* op = g_o + ((size_t)f * 512 + row) * 512 + n * 32;
    #pragma unroll
    for (int j4 = 0; j4 < 8; j4++) {
        float4 v = make_float4(o[j4*4+0]*inv, o[j4*4+1]*inv, o[j4*4+2]*inv, o[j4*4+3]*inv);
        *(float4*)(op + j4 * 4) = v;
    }
}

// ---------------- launcher ----------------
extern "C" void kernel_launch(void* const* d_in, const int* in_sizes, int n_in,
                              void* d_out, int out_size)
{
    const float* hidden = (const float*)d_in[0];   // (2,4096,512)
    const float* W      = (const float*)d_in[1];   // (1536,512)
    const float* bias   = (const float*)d_in[2];   // (1536)
    const float* Wo     = (const float*)d_in[3];   // (512,512)
    const float* bo     = (const float*)d_in[4];   // (512)
    const float* te     = (const float*)d_in[5];   // (4,512)
    float* out = (float*)d_out;

    float *p_qkv, *p_q, *p_k, *p_v, *p_qh, *p_o, *p_kp, *p_vp;
    cudaGetSymbolAddress((void**)&p_qkv, g_qkv);
    cudaGetSymbolAddress((void**)&p_q,   g_q);
    cudaGetSymbolAddress((void**)&p_k,   g_k);
    cudaGetSymbolAddress((void**)&p_v,   g_v);
    cudaGetSymbolAddress((void**)&p_qh,  g_qh);
    cudaGetSymbolAddress((void**)&p_o,   g_o);
    cudaGetSymbolAddress((void**)&p_kp,  g_kp);
    cudaGetSymbolAddress((void**)&p_vp,  g_vp);

    // 1) qkv = hidden @ in_proj_W^T + b   (8192 x 1536, K=512)
    gemm_nt<<<dim3(1536 / 64, 8192 / 64), 256>>>(hidden, W, bias, p_qkv, 1536, 512, 0);

    // 2) RoPE + stream reorder into g_q/g_k/g_v
    rope_reorder<<<8192, 256>>>(p_qkv);

    // 3) pad frames of kproj/vproj = bias (projected zero rows)
    fill_pad<<<(2 * 3 * 512 * 512) / 256, 256>>>(bias);

    // 4) teK = temporal_embed @ Wk^T
    compute_teK<<<dim3(8, 4), 64>>>(te, W);

    // 5) qh = q_mha @ Wq^T + bq
    gemm_nt<<<dim3(8, 128), 256>>>(p_q, W, bias, p_qh, 512, 512, 0);
    // 6) kproj (padded) = k_comb @ Wk^T + bk
    gemm_nt<<<dim3(8, 128), 256>>>(p_k, W + 512 * 512, bias + 512, p_kp, 512, 512, 1);
    // 7) vproj (padded) = v_comb @ Wv^T + bv
    gemm_nt<<<dim3(8, 128), 256>>>(p_v, W + 1024 * 512, bias + 1024, p_vp, 512, 512, 1);

    // 8) sliding-window attention
    attn_kernel<<<dim3(4, 16, 16), 128>>>();

    // 9) out = o @ Wo^T + bo  (row order == d_out layout)
    gemm_nt<<<dim3(8, 128), 256>>>(p_o, Wo, bo, out, 512, 512, 0);
}

// round 4
// speedup vs baseline: 1.3873x; 1.3573x over previous
#include <cuda_runtime.h>
#include <cuda_bf16.h>
#include <mma.h>
#include <math.h>
#include <cstdint>

using namespace nvcuda;

// ---------------- problem constants ----------------
// B=2, T=8, H=16, W=16, E=512, n_heads=16, d=32, S=4096, L2=512, WINDOW=4
// frames BT=16, padded frames per batch TPAD=11, K of all GEMMs = 512

// ---------------- device scratch ----------------
__device__ __align__(128) float g_qkv[8192ull * 1536];        // fp32 qkv
__device__ __align__(128) float g_qh [16ull * 512 * 512];     // second-proj q (attn input)
__device__ __align__(128) float g_kp [2ull * 11 * 512 * 512]; // padded proj k
__device__ __align__(128) float g_vp [2ull * 11 * 512 * 512]; // padded proj v
__device__ __align__(128) float g_teK[4 * 512];

// bf16 hi/lo split operands for tensor-core GEMMs
__device__ __align__(128) __nv_bfloat16 g_hh [8192ull * 512], g_hl [8192ull * 512]; // hidden
__device__ __align__(128) __nv_bfloat16 g_Wh [1536ull * 512], g_Wl [1536ull * 512]; // in_proj W
__device__ __align__(128) __nv_bfloat16 g_Woh[ 512ull * 512], g_Wol[ 512ull * 512]; // out_proj W
__device__ __align__(128) __nv_bfloat16 g_qbh[8192ull * 512], g_qbl[8192ull * 512]; // roped q
__device__ __align__(128) __nv_bfloat16 g_kbh[8192ull * 512], g_kbl[8192ull * 512]; // roped k
__device__ __align__(128) __nv_bfloat16 g_vbh[8192ull * 512], g_vbl[8192ull * 512]; // v
__device__ __align__(128) __nv_bfloat16 g_obh[8192ull * 512], g_obl[8192ull * 512]; // attn out

// ---------------- helpers ----------------
__device__ __forceinline__ void split2(float x, float y,
                                       __nv_bfloat162& h, __nv_bfloat162& l) {
    __nv_bfloat16 hx = __float2bfloat16_rn(x);
    __nv_bfloat16 hy = __float2bfloat16_rn(y);
    h = __halves2bfloat162(hx, hy);
    l = __halves2bfloat162(__float2bfloat16_rn(x - __bfloat162float(hx)),
                           __float2bfloat16_rn(y - __bfloat162float(hy)));
}

// f32x2 packed FMA helpers (verified: compiles on compute_103)
__device__ __forceinline__ unsigned long long f2pk(float x, float y) {
    unsigned long long r; asm("mov.b64 %0, {%1, %2};" : "=l"(r) : "f"(x), "f"(y)); return r;
}
__device__ __forceinline__ unsigned long long ffma2(unsigned long long a, unsigned long long b,
                                                    unsigned long long c) {
    unsigned long long d; asm("fma.rn.f32x2 %0, %1, %2, %3;" : "=l"(d) : "l"(a), "l"(b), "l"(c));
    return d;
}
__device__ __forceinline__ float2 f2up(unsigned long long v) {
    float2 r; asm("mov.b64 {%0, %1}, %2;" : "=f"(r.x), "=f"(r.y) : "l"(v)); return r;
}

// ---------------- elementwise bf16 split ----------------
__global__ void split_bf16(const float* __restrict__ src,
                           __nv_bfloat16* __restrict__ hi, __nv_bfloat16* __restrict__ lo)
{
    size_t i = ((size_t)blockIdx.x * 256 + threadIdx.x) * 4;
    float4 v = *(const float4*)(src + i);
    __nv_bfloat162 h0, l0, h1, l1;
    split2(v.x, v.y, h0, l0);
    split2(v.z, v.w, h1, l1);
    *(__nv_bfloat162*)(hi + i)     = h0;
    *(__nv_bfloat162*)(hi + i + 2) = h1;
    *(__nv_bfloat162*)(lo + i)     = l0;
    *(__nv_bfloat162*)(lo + i + 2) = l1;
}

// ---------------- wmma bf16-split GEMM ----------------
// C[M,N] = A[M,512] @ B[N,512]^T + bias, with A=Ahi+Alo, B=Bhi+Blo (bf16 split),
// fp32 accumulation of hi*hi + hi*lo + lo*hi. Tile 128x128, BK=32, 256 threads.
// pad_remap: out_row = r + (r>>12 + 1)*1536 (3 leading pad frames per batch).
__global__ void __launch_bounds__(256) gemm_wmma(
    const __nv_bfloat16* __restrict__ Ahi, const __nv_bfloat16* __restrict__ Alo,
    const __nv_bfloat16* __restrict__ Bhi, const __nv_bfloat16* __restrict__ Blo,
    const float* __restrict__ bias, float* __restrict__ C, int N, int pad_remap)
{
    __shared__ __align__(16) __nv_bfloat16 sAh[128 * 40], sAl[128 * 40];
    __shared__ __align__(16) __nv_bfloat16 sBh[128 * 40], sBl[128 * 40];

    const int tid = threadIdx.x, w = tid >> 5, lane = tid & 31;
    const int m0 = blockIdx.y * 128, n0 = blockIdx.x * 128;
    const int wm = (w >> 2) * 64, wn = (w & 3) * 32;
    const int lrow = tid >> 1, lcol = (tid & 1) * 16;
    const size_t aoff = (size_t)(m0 + lrow) * 512 + lcol;
    const size_t boff = (size_t)(n0 + lrow) * 512 + lcol;
    const int soff = lrow * 40 + lcol;

    wmma::fragment<wmma::accumulator, 16, 16, 16, float> fc[4][2];
    #pragma unroll
    for (int i = 0; i < 4; i++)
        #pragma unroll
        for (int j = 0; j < 2; j++) wmma::fill_fragment(fc[i][j], 0.f);

    uint4 rah0, rah1, ral0, ral1, rbh0, rbh1, rbl0, rbl1;
    auto LD = [&](int k0) {
        rah0 = *(const uint4*)(Ahi + aoff + k0); rah1 = *(const uint4*)(Ahi + aoff + k0 + 8);
        ral0 = *(const uint4*)(Alo + aoff + k0); ral1 = *(const uint4*)(Alo + aoff + k0 + 8);
        rbh0 = *(const uint4*)(Bhi + boff + k0); rbh1 = *(const uint4*)(Bhi + boff + k0 + 8);
        rbl0 = *(const uint4*)(Blo + boff + k0); rbl1 = *(const uint4*)(Blo + boff + k0 + 8);
    };
    LD(0);

    for (int k0 = 0; k0 < 512; k0 += 32) {
        *(uint4*)&sAh[soff] = rah0; *(uint4*)&sAh[soff + 8] = rah1;
        *(uint4*)&sAl[soff] = ral0; *(uint4*)&sAl[soff + 8] = ral1;
        *(uint4*)&sBh[soff] = rbh0; *(uint4*)&sBh[soff + 8] = rbh1;
        *(uint4*)&sBl[soff] = rbl0; *(uint4*)&sBl[soff + 8] = rbl1;
        __syncthreads();
        if (k0 + 32 < 512) LD(k0 + 32);   // overlap next loads with MMA

        #pragma unroll
        for (int ks = 0; ks < 32; ks += 16) {
            wmma::fragment<wmma::matrix_a, 16, 16, 16, __nv_bfloat16, wmma::row_major> fah[4], fal[4];
            wmma::fragment<wmma::matrix_b, 16, 16, 16, __nv_bfloat16, wmma::col_major> fbh[2], fbl[2];
            #pragma unroll
            for (int i = 0; i < 4; i++) {
                wmma::load_matrix_sync(fah[i], &sAh[(wm + i * 16) * 40 + ks], 40);
                wmma::load_matrix_sync(fal[i], &sAl[(wm + i * 16) * 40 + ks], 40);
            }
            #pragma unroll
            for (int j = 0; j < 2; j++) {
                wmma::load_matrix_sync(fbh[j], &sBh[(wn + j * 16) * 40 + ks], 40);
                wmma::load_matrix_sync(fbl[j], &sBl[(wn + j * 16) * 40 + ks], 40);
            }
            #pragma unroll
            for (int i = 0; i < 4; i++)
                #pragma unroll
                for (int j = 0; j < 2; j++) {
                    wmma::mma_sync(fc[i][j], fah[i], fbh[j], fc[i][j]);
                    wmma::mma_sync(fc[i][j], fah[i], fbl[j], fc[i][j]);
                    wmma::mma_sync(fc[i][j], fal[i], fbh[j], fc[i][j]);
                }
        }
        __syncthreads();
    }

    // epilogue: stage each 16x16 frag in (reused) smem, add bias, write with remap
    float* cst = reinterpret_cast<float*>(sAh) + w * 256;   // 1KB per warp inside sAh
    const int er = lane >> 1, ec = (lane & 1) * 8;
    #pragma unroll
    for (int i = 0; i < 4; i++)
        #pragma unroll
        for (int j = 0; j < 2; j++) {
            wmma::store_matrix_sync(cst, fc[i][j], 16, wmma::mem_row_major);
            __syncwarp();
            int gr = m0 + wm + i * 16 + er;
            int out_r = pad_remap ? (gr + ((gr >> 12) + 1) * 1536) : gr;
            int gn = n0 + wn + j * 16 + ec;
            float4 v0 = *(float4*)&cst[er * 16 + ec];
            float4 v1 = *(float4*)&cst[er * 16 + ec + 4];
            float4 b0 = *(const float4*)(bias + gn);
            float4 b1 = *(const float4*)(bias + gn + 4);
            v0.x += b0.x; v0.y += b0.y; v0.z += b0.z; v0.w += b0.w;
            v1.x += b1.x; v1.y += b1.y; v1.z += b1.z; v1.w += b1.w;
            float* crow = C + (size_t)out_r * N + gn;
            *(float4*)crow = v0;
            *(float4*)(crow + 4) = v1;
            __syncwarp();
        }
}

// ---------------- RoPE + stream reorder (emits bf16 hi/lo directly) ----------------
__global__ void rope_reorder(const float* __restrict__ qkv)
{
    int token = blockIdx.x;            // b*4096 + s
    int b = token >> 12;
    int s = token & 4095;
    int p = threadIdx.x;               // pair 0..255 over E
    int j = p & 15;

    int tqk, lqk, fidx;
    float pos;
    if (s < 2048) {
        tqk = s >> 8; lqk = s & 255;
        fidx = j; pos = (float)lqk;
    } else {
        int s2 = s - 2048;
        tqk = s2 >> 8;
        int pp = s2 & 255;
        lqk = 256 + pp;
        int h = pp >> 4, w = pp & 15;
        if (j < 8) { fidx = 2 * j;           pos = (float)h; }
        else       { fidx = 2 * (j - 8) + 1; pos = (float)w; }
    }
    float freq = __powf(10000.0f, -(float)fidx * (1.0f / 16.0f));
    float ang = pos * freq;
    float sn, cs;
    sincosf(ang, &sn, &cs);

    const float* row = qkv + (size_t)token * 1536;
    int frame = b * 8 + tqk;
    size_t ob = ((size_t)frame * 512 + lqk) * 512 + 2 * p;

    __nv_bfloat162 h2, l2;
    float2 qv = *(const float2*)(row + 2 * p);
    split2(qv.x * cs - qv.y * sn, qv.x * sn + qv.y * cs, h2, l2);
    *(__nv_bfloat162*)(g_qbh + ob) = h2;
    *(__nv_bfloat162*)(g_qbl + ob) = l2;

    float2 kv = *(const float2*)(row + 512 + 2 * p);
    split2(kv.x * cs - kv.y * sn, kv.x * sn + kv.y * cs, h2, l2);
    *(__nv_bfloat162*)(g_kbh + ob) = h2;
    *(__nv_bfloat162*)(g_kbl + ob) = l2;

    // v: straight reshape (different frame mapping), no rope
    float2 vv = *(const float2*)(row + 1024 + 2 * p);
    size_t vb = ((size_t)(b * 8 + (s >> 9)) * 512 + (s & 511)) * 512 + 2 * p;
    split2(vv.x, vv.y, h2, l2);
    *(__nv_bfloat162*)(g_vbh + vb) = h2;
    *(__nv_bfloat162*)(g_vbl + vb) = l2;
}

// ---------------- pad frames = projected zero rows (bias) ----------------
__global__ void fill_pad(const float* __restrict__ bias)
{
    int idx = blockIdx.x * 256 + threadIdx.x;
    int e = idx & 511;
    int rl = idx >> 9;
    int b = rl / 1536;
    int rem = rl - b * 1536;
    size_t o = ((size_t)b * 11 * 512 + rem) * 512 + e;
    g_kp[o] = bias[512 + e];
    g_vp[o] = bias[1024 + e];
}

// ---------------- teK[i][e] = temporal_embed[i] . Wk[e] ----------------
__global__ void compute_teK(const float* __restrict__ te, const float* __restrict__ W)
{
    int i = blockIdx.y;
    int e = blockIdx.x * 128 + threadIdx.x;
    const float4* wk = (const float4*)(W + (size_t)(512 + e) * 512);
    const float4* tr = (const float4*)(te + i * 512);
    float s = 0.f;
    #pragma unroll 8
    for (int k = 0; k < 128; k++) {
        float4 a = tr[k], b = wk[k];
        s += a.x * b.x + a.y * b.y + a.z * b.z + a.w * b.w;
    }
    g_teK[i * 512 + e] = s;
}

// ---------------- flash attention (branchless softmax, f32x2 packed FMA) ----------------
__global__ void attn_kernel()
{
    int f = blockIdx.z, n = blockIdx.y;
    int row = blockIdx.x * 128 + threadIdx.x;
    int b = f >> 3, t = f & 7;

    __shared__ __align__(16) float Ks[64 * 32];
    __shared__ __align__(16) float Vs[64 * 32];

    const float scale = 0.17677669529663689f;  // 1/sqrt(32)
    unsigned long long q2[16], o2[16];
    const float* qp = g_qh + ((size_t)f * 512 + row) * 512 + n * 32;
    #pragma unroll
    for (int j4 = 0; j4 < 8; j4++) {
        float4 v = *(const float4*)(qp + j4 * 4);
        q2[j4 * 2 + 0] = f2pk(v.x * scale, v.y * scale);
        q2[j4 * 2 + 1] = f2pk(v.z * scale, v.w * scale);
    }
    const unsigned long long zero2 = f2pk(0.f, 0.f);
    #pragma unroll
    for (int j = 0; j < 16; j++) o2[j] = zero2;
    float lsum = 0.f;

    for (int cc = 0; cc < 32; cc++) {
        int i = cc >> 3;
        int lbase = (cc & 7) * 64;
        size_t fr = (size_t)(b * 11 + t + i);
        const float* kbase = g_kp + (fr * 512 + lbase) * 512 + n * 32;
        const float* vbase = g_vp + (fr * 512 + lbase) * 512 + n * 32;
        const float* tek   = g_teK + i * 512 + n * 32;

        __syncthreads();
        #pragma unroll
        for (int u = 0; u < 4; u++) {
            int pidx = threadIdx.x + u * 128;
            int l = pidx >> 3, d4 = pidx & 7;
            float4 kv = *(const float4*)(kbase + (size_t)l * 512 + d4 * 4);
            float4 tv = *(const float4*)(tek + d4 * 4);
            kv.x += tv.x; kv.y += tv.y; kv.z += tv.z; kv.w += tv.w;
            *(float4*)&Ks[pidx * 4] = kv;
            *(float4*)&Vs[pidx * 4] = *(const float4*)(vbase + (size_t)l * 512 + d4 * 4);
        }
        __syncthreads();

        #pragma unroll 2
        for (int kk = 0; kk < 64; kk++) {
            const unsigned long long* kp = (const unsigned long long*)(Ks + kk * 32);
            unsigned long long acc = zero2;
            #pragma unroll
            for (int j = 0; j < 16; j++) acc = ffma2(q2[j], kp[j], acc);
            float2 av = f2up(acc);
            float s = av.x + av.y;
            float p = __expf(s);
            lsum += p;
            unsigned long long p2 = f2pk(p, p);
            const unsigned long long* vp = (const unsigned long long*)(Vs + kk * 32);
            #pragma unroll
            for (int j = 0; j < 16; j++) o2[j] = ffma2(p2, vp[j], o2[j]);
        }
    }

    float inv = 1.f / lsum;
    size_t obase = ((size_t)f * 512 + row) * 512 + n * 32;
    #pragma unroll
    for (int j = 0; j < 8; j++) {
        float2 a = f2up(o2[j * 2 + 0]);
        float2 c = f2up(o2[j * 2 + 1]);
        __nv_bfloat162 h0, l0, h1, l1;
        split2(a.x * inv, a.y * inv, h0, l0);
        split2(c.x * inv, c.y * inv, h1, l1);
        *(__nv_bfloat162*)(g_obh + obase + j * 4)     = h0;
        *(__nv_bfloat162*)(g_obh + obase + j * 4 + 2) = h1;
        *(__nv_bfloat162*)(g_obl + obase + j * 4)     = l0;
        *(__nv_bfloat162*)(g_obl + obase + j * 4 + 2) = l1;
    }
}

// ---------------- launcher ----------------
extern "C" void kernel_launch(void* const* d_in, const int* in_sizes, int n_in,
                              void* d_out, int out_size)
{
    const float* hidden = (const float*)d_in[0];
    const float* W      = (const float*)d_in[1];
    const float* bias   = (const float*)d_in[2];
    const float* Wo     = (const float*)d_in[3];
    const float* bo     = (const float*)d_in[4];
    const float* te     = (const float*)d_in[5];
    float* out = (float*)d_out;

    float *p_qkv, *p_qh, *p_kp, *p_vp;
    __nv_bfloat16 *p_hh, *p_hl, *p_Wh, *p_Wl, *p_Woh, *p_Wol;
    __nv_bfloat16 *p_qbh, *p_qbl, *p_kbh, *p_kbl, *p_vbh, *p_vbl, *p_obh, *p_obl;
    cudaGetSymbolAddress((void**)&p_qkv, g_qkv);
    cudaGetSymbolAddress((void**)&p_qh,  g_qh);
    cudaGetSymbolAddress((void**)&p_kp,  g_kp);
    cudaGetSymbolAddress((void**)&p_vp,  g_vp);
    cudaGetSymbolAddress((void**)&p_hh,  g_hh);   cudaGetSymbolAddress((void**)&p_hl,  g_hl);
    cudaGetSymbolAddress((void**)&p_Wh,  g_Wh);   cudaGetSymbolAddress((void**)&p_Wl,  g_Wl);
    cudaGetSymbolAddress((void**)&p_Woh, g_Woh);  cudaGetSymbolAddress((void**)&p_Wol, g_Wol);
    cudaGetSymbolAddress((void**)&p_qbh, g_qbh);  cudaGetSymbolAddress((void**)&p_qbl, g_qbl);
    cudaGetSymbolAddress((void**)&p_kbh, g_kbh);  cudaGetSymbolAddress((void**)&p_kbl, g_kbl);
    cudaGetSymbolAddress((void**)&p_vbh, g_vbh);  cudaGetSymbolAddress((void**)&p_vbl, g_vbl);
    cudaGetSymbolAddress((void**)&p_obh, g_obh);  cudaGetSymbolAddress((void**)&p_obl, g_obl);

    // 0) split inputs into bf16 hi/lo
    split_bf16<<<8192 * 512 / 1024, 256>>>(hidden, p_hh, p_hl);
    split_bf16<<<1536 * 512 / 1024, 256>>>(W, p_Wh, p_Wl);
    split_bf16<<< 512 * 512 / 1024, 256>>>(Wo, p_Woh, p_Wol);

    // 1) qkv = hidden @ in_proj_W^T + b   (8192 x 1536, K=512)
    gemm_wmma<<<dim3(12, 64), 256>>>(p_hh, p_hl, p_Wh, p_Wl, bias, p_qkv, 1536, 0);

    // 2) RoPE + stream reorder (emits bf16 hi/lo q,k,v)
    rope_reorder<<<8192, 256>>>(p_qkv);

    // 3) pad frames of kproj/vproj = bias
    fill_pad<<<(2 * 3 * 512 * 512) / 256, 256>>>(bias);

    // 4) teK = temporal_embed @ Wk^T
    compute_teK<<<dim3(4, 4), 128>>>(te, W);

    // 5) qh = q_mha @ Wq^T + bq
    gemm_wmma<<<dim3(4, 64), 256>>>(p_qbh, p_qbl, p_Wh, p_Wl, bias, p_qh, 512, 0);
    // 6) kproj (padded) = k_comb @ Wk^T + bk
    gemm_wmma<<<dim3(4, 64), 256>>>(p_kbh, p_kbl, p_Wh + 512 * 512, p_Wl + 512 * 512,
                                    bias + 512, p_kp, 512, 1);
    // 7) vproj (padded) = v_comb @ Wv^T + bv
    gemm_wmma<<<dim3(4, 64), 256>>>(p_vbh, p_vbl, p_Wh + 1024 * 512, p_Wl + 1024 * 512,
                                    bias + 1024, p_vp, 512, 1);

    // 8) sliding-window attention (emits bf16 hi/lo o)
    attn_kernel<<<dim3(4, 16, 16), 128>>>();

    // 9) out = o @ Wo^T + bo
    gemm_wmma<<<dim3(4, 64), 256>>>(p_obh, p_obl, p_Woh, p_Wol, bo, out, 512, 0);
}

// round 5
// speedup vs baseline: 2.2011x; 1.5866x over previous
#include <cuda_runtime.h>
#include <cuda_bf16.h>
#include <mma.h>
#include <math.h>
#include <cstdint>

using namespace nvcuda;

// ---------------- problem constants ----------------
// B=2, T=8, H=16, W=16, E=512, n_heads=16, d=32, S=4096, L2=512, WINDOW=4
// frames BT=16, padded frames per batch TPAD=11, K of all GEMMs = 512

// ---------------- device scratch ----------------
__device__ __align__(128) float g_qkv[8192ull * 1536];        // fp32 qkv
__device__ __align__(128) float g_qh [16ull * 512 * 512];     // second-proj q (attn input)
__device__ __align__(128) float g_kp [2ull * 11 * 512 * 512]; // padded proj k
__device__ __align__(128) float g_vp [2ull * 11 * 512 * 512]; // padded proj v
__device__ __align__(128) float g_teK[4 * 512];

// bf16 hi/lo split operands for tensor-core GEMMs
__device__ __align__(128) __nv_bfloat16 g_hh [8192ull * 512], g_hl [8192ull * 512]; // hidden
__device__ __align__(128) __nv_bfloat16 g_Wh [1536ull * 512], g_Wl [1536ull * 512]; // in_proj W
__device__ __align__(128) __nv_bfloat16 g_Woh[ 512ull * 512], g_Wol[ 512ull * 512]; // out_proj W
__device__ __align__(128) __nv_bfloat16 g_qbh[8192ull * 512], g_qbl[8192ull * 512]; // roped q
__device__ __align__(128) __nv_bfloat16 g_kbh[8192ull * 512], g_kbl[8192ull * 512]; // roped k
__device__ __align__(128) __nv_bfloat16 g_vbh[8192ull * 512], g_vbl[8192ull * 512]; // v
__device__ __align__(128) __nv_bfloat16 g_obh[8192ull * 512], g_obl[8192ull * 512]; // attn out

// ---------------- helpers ----------------
__device__ __forceinline__ void split2(float x, float y,
                                       __nv_bfloat162& h, __nv_bfloat162& l) {
    __nv_bfloat16 hx = __float2bfloat16_rn(x);
    __nv_bfloat16 hy = __float2bfloat16_rn(y);
    h = __halves2bfloat162(hx, hy);
    l = __halves2bfloat162(__float2bfloat16_rn(x - __bfloat162float(hx)),
                           __float2bfloat16_rn(y - __bfloat162float(hy)));
}

__device__ __forceinline__ void split4(float4 v, uint32_t& h0, uint32_t& h1,
                                       uint32_t& l0, uint32_t& l1) {
    __nv_bfloat162 a, b, c, d;
    split2(v.x, v.y, a, c);
    split2(v.z, v.w, b, d);
    h0 = *(uint32_t*)&a; h1 = *(uint32_t*)&b;
    l0 = *(uint32_t*)&c; l1 = *(uint32_t*)&d;
}

__device__ __forceinline__ uint32_t bfpack_hi(float x, float y) {
    __nv_bfloat162 h = __floats2bfloat162_rn(x, y);
    return *(uint32_t*)&h;
}
__device__ __forceinline__ uint32_t bfpack_lo(float x, float y) {
    float rx = __bfloat162float(__float2bfloat16_rn(x));
    float ry = __bfloat162float(__float2bfloat16_rn(y));
    __nv_bfloat162 l = __floats2bfloat162_rn(x - rx, y - ry);
    return *(uint32_t*)&l;
}

__device__ __forceinline__ uint32_t smem_u32(const void* p) {
    uint32_t a;
    asm("{ .reg .u64 t; cvta.to.shared.u64 t, %1; cvt.u32.u64 %0, t; }" : "=r"(a) : "l"(p));
    return a;
}

__device__ __forceinline__ void ldsm_x4(uint32_t* r, uint32_t addr) {
    asm volatile("ldmatrix.sync.aligned.m8n8.x4.shared.b16 {%0,%1,%2,%3}, [%4];"
        : "=r"(r[0]), "=r"(r[1]), "=r"(r[2]), "=r"(r[3]) : "r"(addr));
}
__device__ __forceinline__ void ldsm_x2(uint32_t& r0, uint32_t& r1, uint32_t addr) {
    asm volatile("ldmatrix.sync.aligned.m8n8.x2.shared.b16 {%0,%1}, [%2];"
        : "=r"(r0), "=r"(r1) : "r"(addr));
}
__device__ __forceinline__ void ldsm_x2t(uint32_t& r0, uint32_t& r1, uint32_t addr) {
    asm volatile("ldmatrix.sync.aligned.m8n8.x2.trans.shared.b16 {%0,%1}, [%2];"
        : "=r"(r0), "=r"(r1) : "r"(addr));
}
__device__ __forceinline__ void mma16816(float* d, const uint32_t* a, uint32_t b0, uint32_t b1) {
    asm volatile("mma.sync.aligned.m16n8k16.row.col.f32.bf16.bf16.f32 "
        "{%0,%1,%2,%3}, {%4,%5,%6,%7}, {%8,%9}, {%0,%1,%2,%3};"
        : "+f"(d[0]), "+f"(d[1]), "+f"(d[2]), "+f"(d[3])
        : "r"(a[0]), "r"(a[1]), "r"(a[2]), "r"(a[3]), "r"(b0), "r"(b1));
}

// ---------------- elementwise bf16 split ----------------
__global__ void split_bf16(const float* __restrict__ src,
                           __nv_bfloat16* __restrict__ hi, __nv_bfloat16* __restrict__ lo)
{
    size_t i = ((size_t)blockIdx.x * 256 + threadIdx.x) * 4;
    float4 v = *(const float4*)(src + i);
    __nv_bfloat162 h0, l0, h1, l1;
    split2(v.x, v.y, h0, l0);
    split2(v.z, v.w, h1, l1);
    *(__nv_bfloat162*)(hi + i)     = h0;
    *(__nv_bfloat162*)(hi + i + 2) = h1;
    *(__nv_bfloat162*)(lo + i)     = l0;
    *(__nv_bfloat162*)(lo + i + 2) = l1;
}

// ---------------- wmma bf16-split GEMM (unchanged from R4, passing) ----------------
__global__ void __launch_bounds__(256) gemm_wmma(
    const __nv_bfloat16* __restrict__ Ahi, const __nv_bfloat16* __restrict__ Alo,
    const __nv_bfloat16* __restrict__ Bhi, const __nv_bfloat16* __restrict__ Blo,
    const float* __restrict__ bias, float* __restrict__ C, int N, int pad_remap)
{
    __shared__ __align__(16) __nv_bfloat16 sAh[128 * 40], sAl[128 * 40];
    __shared__ __align__(16) __nv_bfloat16 sBh[128 * 40], sBl[128 * 40];

    const int tid = threadIdx.x, w = tid >> 5, lane = tid & 31;
    const int m0 = blockIdx.y * 128, n0 = blockIdx.x * 128;
    const int wm = (w >> 2) * 64, wn = (w & 3) * 32;
    const int lrow = tid >> 1, lcol = (tid & 1) * 16;
    const size_t aoff = (size_t)(m0 + lrow) * 512 + lcol;
    const size_t boff = (size_t)(n0 + lrow) * 512 + lcol;
    const int soff = lrow * 40 + lcol;

    wmma::fragment<wmma::accumulator, 16, 16, 16, float> fc[4][2];
    #pragma unroll
    for (int i = 0; i < 4; i++)
        #pragma unroll
        for (int j = 0; j < 2; j++) wmma::fill_fragment(fc[i][j], 0.f);

    uint4 rah0, rah1, ral0, ral1, rbh0, rbh1, rbl0, rbl1;
    auto LD = [&](int k0) {
        rah0 = *(const uint4*)(Ahi + aoff + k0); rah1 = *(const uint4*)(Ahi + aoff + k0 + 8);
        ral0 = *(const uint4*)(Alo + aoff + k0); ral1 = *(const uint4*)(Alo + aoff + k0 + 8);
        rbh0 = *(const uint4*)(Bhi + boff + k0); rbh1 = *(const uint4*)(Bhi + boff + k0 + 8);
        rbl0 = *(const uint4*)(Blo + boff + k0); rbl1 = *(const uint4*)(Blo + boff + k0 + 8);
    };
    LD(0);

    for (int k0 = 0; k0 < 512; k0 += 32) {
        *(uint4*)&sAh[soff] = rah0; *(uint4*)&sAh[soff + 8] = rah1;
        *(uint4*)&sAl[soff] = ral0; *(uint4*)&sAl[soff + 8] = ral1;
        *(uint4*)&sBh[soff] = rbh0; *(uint4*)&sBh[soff + 8] = rbh1;
        *(uint4*)&sBl[soff] = rbl0; *(uint4*)&sBl[soff + 8] = rbl1;
        __syncthreads();
        if (k0 + 32 < 512) LD(k0 + 32);

        #pragma unroll
        for (int ks = 0; ks < 32; ks += 16) {
            wmma::fragment<wmma::matrix_a, 16, 16, 16, __nv_bfloat16, wmma::row_major> fah[4], fal[4];
            wmma::fragment<wmma::matrix_b, 16, 16, 16, __nv_bfloat16, wmma::col_major> fbh[2], fbl[2];
            #pragma unroll
            for (int i = 0; i < 4; i++) {
                wmma::load_matrix_sync(fah[i], &sAh[(wm + i * 16) * 40 + ks], 40);
                wmma::load_matrix_sync(fal[i], &sAl[(wm + i * 16) * 40 + ks], 40);
            }
            #pragma unroll
            for (int j = 0; j < 2; j++) {
                wmma::load_matrix_sync(fbh[j], &sBh[(wn + j * 16) * 40 + ks], 40);
                wmma::load_matrix_sync(fbl[j], &sBl[(wn + j * 16) * 40 + ks], 40);
            }
            #pragma unroll
            for (int i = 0; i < 4; i++)
                #pragma unroll
                for (int j = 0; j < 2; j++) {
                    wmma::mma_sync(fc[i][j], fah[i], fbh[j], fc[i][j]);
                    wmma::mma_sync(fc[i][j], fah[i], fbl[j], fc[i][j]);
                    wmma::mma_sync(fc[i][j], fal[i], fbh[j], fc[i][j]);
                }
        }
        __syncthreads();
    }

    float* cst = reinterpret_cast<float*>(sAh) + w * 256;
    const int er = lane >> 1, ec = (lane & 1) * 8;
    #pragma unroll
    for (int i = 0; i < 4; i++)
        #pragma unroll
        for (int j = 0; j < 2; j++) {
            wmma::store_matrix_sync(cst, fc[i][j], 16, wmma::mem_row_major);
            __syncwarp();
            int gr = m0 + wm + i * 16 + er;
            int out_r = pad_remap ? (gr + ((gr >> 12) + 1) * 1536) : gr;
            int gn = n0 + wn + j * 16 + ec;
            float4 v0 = *(float4*)&cst[er * 16 + ec];
            float4 v1 = *(float4*)&cst[er * 16 + ec + 4];
            float4 b0 = *(const float4*)(bias + gn);
            float4 b1 = *(const float4*)(bias + gn + 4);
            v0.x += b0.x; v0.y += b0.y; v0.z += b0.z; v0.w += b0.w;
            v1.x += b1.x; v1.y += b1.y; v1.z += b1.z; v1.w += b1.w;
            float* crow = C + (size_t)out_r * N + gn;
            *(float4*)crow = v0;
            *(float4*)(crow + 4) = v1;
            __syncwarp();
        }
}

// ---------------- RoPE + stream reorder (emits bf16 hi/lo) ----------------
__global__ void rope_reorder(const float* __restrict__ qkv)
{
    int token = blockIdx.x;
    int b = token >> 12;
    int s = token & 4095;
    int p = threadIdx.x;
    int j = p & 15;

    int tqk, lqk, fidx;
    float pos;
    if (s < 2048) {
        tqk = s >> 8; lqk = s & 255;
        fidx = j; pos = (float)lqk;
    } else {
        int s2 = s - 2048;
        tqk = s2 >> 8;
        int pp = s2 & 255;
        lqk = 256 + pp;
        int h = pp >> 4, w = pp & 15;
        if (j < 8) { fidx = 2 * j;           pos = (float)h; }
        else       { fidx = 2 * (j - 8) + 1; pos = (float)w; }
    }
    float freq = __powf(10000.0f, -(float)fidx * (1.0f / 16.0f));
    float ang = pos * freq;
    float sn, cs;
    sincosf(ang, &sn, &cs);

    const float* row = qkv + (size_t)token * 1536;
    int frame = b * 8 + tqk;
    size_t ob = ((size_t)frame * 512 + lqk) * 512 + 2 * p;

    __nv_bfloat162 h2, l2;
    float2 qv = *(const float2*)(row + 2 * p);
    split2(qv.x * cs - qv.y * sn, qv.x * sn + qv.y * cs, h2, l2);
    *(__nv_bfloat162*)(g_qbh + ob) = h2;
    *(__nv_bfloat162*)(g_qbl + ob) = l2;

    float2 kv = *(const float2*)(row + 512 + 2 * p);
    split2(kv.x * cs - kv.y * sn, kv.x * sn + kv.y * cs, h2, l2);
    *(__nv_bfloat162*)(g_kbh + ob) = h2;
    *(__nv_bfloat162*)(g_kbl + ob) = l2;

    float2 vv = *(const float2*)(row + 1024 + 2 * p);
    size_t vb = ((size_t)(b * 8 + (s >> 9)) * 512 + (s & 511)) * 512 + 2 * p;
    split2(vv.x, vv.y, h2, l2);
    *(__nv_bfloat162*)(g_vbh + vb) = h2;
    *(__nv_bfloat162*)(g_vbl + vb) = l2;
}

// ---------------- pad frames = projected zero rows (bias) ----------------
__global__ void fill_pad(const float* __restrict__ bias)
{
    int idx = blockIdx.x * 256 + threadIdx.x;
    int e = idx & 511;
    int rl = idx >> 9;
    int b = rl / 1536;
    int rem = rl - b * 1536;
    size_t o = ((size_t)b * 11 * 512 + rem) * 512 + e;
    g_kp[o] = bias[512 + e];
    g_vp[o] = bias[1024 + e];
}

// ---------------- teK[i][e] = temporal_embed[i] . Wk[e] ----------------
__global__ void compute_teK(const float* __restrict__ te, const float* __restrict__ W)
{
    int i = blockIdx.y;
    int e = blockIdx.x * 128 + threadIdx.x;
    const float4* wk = (const float4*)(W + (size_t)(512 + e) * 512);
    const float4* tr = (const float4*)(te + i * 512);
    float s = 0.f;
    #pragma unroll 8
    for (int k = 0; k < 128; k++) {
        float4 a = tr[k], b = wk[k];
        s += a.x * b.x + a.y * b.y + a.z * b.z + a.w * b.w;
    }
    g_teK[i * 512 + e] = s;
}

// ---------------- tensor-core flash attention (mma.sync m16n8k16 bf16-split) ----------------
// grid (2, 16 heads, 16 frames), 256 threads = 8 warps; warp owns 32 q-rows (2 m-tiles).
// 64 chunks of 32 keys. S = Q@K^T in 3-pass bf16 split; exp + lsum in registers;
// P repacked into A-frags; O += P@V in 3-pass split; O frags live across chunks.
__global__ void __launch_bounds__(256) attn_mma()
{
    const int f = blockIdx.z, head = blockIdx.y;
    const int tid = threadIdx.x, w = tid >> 5, lane = tid & 31;
    const int b = f >> 3, t = f & 7;
    const int n32 = head * 32;
    const int qbase = blockIdx.x * 256 + w * 32;

    __shared__ __align__(16) __nv_bfloat16 sQh[8][16 * 40], sQl[8][16 * 40];
    __shared__ __align__(16) __nv_bfloat16 sKh[32 * 40], sKl[32 * 40];
    __shared__ __align__(16) __nv_bfloat16 sVh[32 * 40], sVl[32 * 40];
    __shared__ float steK[4][32];

    if (tid < 128) steK[tid >> 5][tid & 31] = g_teK[(tid >> 5) * 512 + n32 + (tid & 31)];

    // ---- Q prologue: stage + ldmatrix into registers (hi & lo A-frags) ----
    const float scale = 0.17677669529663689f;  // 1/sqrt(32)
    uint32_t Qh[2][2][4], Ql[2][2][4];
    #pragma unroll
    for (int mt = 0; mt < 2; mt++) {
        int row = lane >> 1, c16 = (lane & 1) * 16;
        const float* qp = g_qh + ((size_t)f * 512 + qbase + mt * 16 + row) * 512 + n32 + c16;
        uint32_t h[8], l[8];
        #pragma unroll
        for (int j = 0; j < 4; j++) {
            float4 v = *(const float4*)(qp + j * 4);
            v.x *= scale; v.y *= scale; v.z *= scale; v.w *= scale;
            split4(v, h[2 * j], h[2 * j + 1], l[2 * j], l[2 * j + 1]);
        }
        int so = row * 40 + c16;
        *(uint4*)&sQh[w][so]     = make_uint4(h[0], h[1], h[2], h[3]);
        *(uint4*)&sQh[w][so + 8] = make_uint4(h[4], h[5], h[6], h[7]);
        *(uint4*)&sQl[w][so]     = make_uint4(l[0], l[1], l[2], l[3]);
        *(uint4*)&sQl[w][so + 8] = make_uint4(l[4], l[5], l[6], l[7]);
        __syncwarp();
        #pragma unroll
        for (int kt = 0; kt < 2; kt++) {
            int qi = (lane % 16) * 40 + kt * 16 + (lane / 16) * 8;
            ldsm_x4(Qh[mt][kt], smem_u32(&sQh[w][qi]));
            ldsm_x4(Ql[mt][kt], smem_u32(&sQl[w][qi]));
        }
        __syncwarp();
    }

    float O[2][4][4];
    float lsum[2][2] = {{0.f, 0.f}, {0.f, 0.f}};
    #pragma unroll
    for (int m = 0; m < 2; m++)
        #pragma unroll
        for (int n = 0; n < 4; n++)
            #pragma unroll
            for (int c = 0; c < 4; c++) O[m][n][c] = 0.f;

    __syncthreads();

    for (int cc = 0; cc < 64; cc++) {
        int slot = cc >> 4, lb = (cc & 15) * 32;
        size_t fr = (size_t)(b * 11 + t + slot);

        // ---- stage K (+teK) and V chunk, bf16 hi/lo split ----
        {
            int r = tid >> 3, c4 = (tid & 7) * 4;
            size_t gb = (fr * 512 + lb + r) * 512 + n32 + c4;
            float4 kv = *(const float4*)(g_kp + gb);
            kv.x += steK[slot][c4];     kv.y += steK[slot][c4 + 1];
            kv.z += steK[slot][c4 + 2]; kv.w += steK[slot][c4 + 3];
            float4 vv = *(const float4*)(g_vp + gb);
            uint32_t h0, h1, l0, l1;
            int so = r * 40 + c4;
            split4(kv, h0, h1, l0, l1);
            *(uint2*)&sKh[so] = make_uint2(h0, h1);
            *(uint2*)&sKl[so] = make_uint2(l0, l1);
            split4(vv, h0, h1, l0, l1);
            *(uint2*)&sVh[so] = make_uint2(h0, h1);
            *(uint2*)&sVl[so] = make_uint2(l0, l1);
        }
        __syncthreads();

        // ---- S = Q @ K^T (3-pass split) ----
        float S[2][4][4];
        #pragma unroll
        for (int m = 0; m < 2; m++)
            #pragma unroll
            for (int n = 0; n < 4; n++)
                #pragma unroll
                for (int c = 0; c < 4; c++) S[m][n][c] = 0.f;

        #pragma unroll
        for (int kt = 0; kt < 2; kt++) {
            #pragma unroll
            for (int nt = 0; nt < 4; nt++) {
                int l = lane & 15;
                int ki = (nt * 8 + (l & 7)) * 40 + kt * 16 + (l >> 3) * 8;
                uint32_t kh0, kh1, kl0, kl1;
                ldsm_x2(kh0, kh1, smem_u32(&sKh[ki]));
                ldsm_x2(kl0, kl1, smem_u32(&sKl[ki]));
                #pragma unroll
                for (int m = 0; m < 2; m++) {
                    mma16816(S[m][nt], Qh[m][kt], kh0, kh1);
                    mma16816(S[m][nt], Qh[m][kt], kl0, kl1);
                    mma16816(S[m][nt], Ql[m][kt], kh0, kh1);
                }
            }
        }

        // ---- exp + lsum (in registers) ----
        #pragma unroll
        for (int m = 0; m < 2; m++)
            #pragma unroll
            for (int n = 0; n < 4; n++) {
                S[m][n][0] = __expf(S[m][n][0]);
                S[m][n][1] = __expf(S[m][n][1]);
                S[m][n][2] = __expf(S[m][n][2]);
                S[m][n][3] = __expf(S[m][n][3]);
                lsum[m][0] += S[m][n][0] + S[m][n][1];
                lsum[m][1] += S[m][n][2] + S[m][n][3];
            }

        // ---- O += P @ V (3-pass split), P frags built from S accumulators ----
        #pragma unroll
        for (int kt = 0; kt < 2; kt++) {
            uint32_t Ph[2][4], Pl[2][4];
            #pragma unroll
            for (int m = 0; m < 2; m++) {
                const float* s0 = S[m][2 * kt];
                const float* s1 = S[m][2 * kt + 1];
                Ph[m][0] = bfpack_hi(s0[0], s0[1]); Pl[m][0] = bfpack_lo(s0[0], s0[1]);
                Ph[m][1] = bfpack_hi(s0[2], s0[3]); Pl[m][1] = bfpack_lo(s0[2], s0[3]);
                Ph[m][2] = bfpack_hi(s1[0], s1[1]); Pl[m][2] = bfpack_lo(s1[0], s1[1]);
                Ph[m][3] = bfpack_hi(s1[2], s1[3]); Pl[m][3] = bfpack_lo(s1[2], s1[3]);
            }
            #pragma unroll
            for (int nt = 0; nt < 4; nt++) {
                int l = lane & 15;
                int vi = (kt * 16 + l) * 40 + nt * 8;
                uint32_t vh0, vh1, vl0, vl1;
                ldsm_x2t(vh0, vh1, smem_u32(&sVh[vi]));
                ldsm_x2t(vl0, vl1, smem_u32(&sVl[vi]));
                #pragma unroll
                for (int m = 0; m < 2; m++) {
                    mma16816(O[m][nt], Ph[m], vh0, vh1);
                    mma16816(O[m][nt], Ph[m], vl0, vl1);
                    mma16816(O[m][nt], Pl[m], vh0, vh1);
                }
            }
        }
        __syncthreads();
    }

    // ---- epilogue: normalize + write bf16 hi/lo ----
    float inv[2][2];
    #pragma unroll
    for (int m = 0; m < 2; m++)
        #pragma unroll
        for (int h = 0; h < 2; h++) {
            float s = lsum[m][h];
            s += __shfl_xor_sync(0xffffffffu, s, 1);
            s += __shfl_xor_sync(0xffffffffu, s, 2);
            inv[m][h] = 1.f / s;
        }
    #pragma unroll
    for (int m = 0; m < 2; m++) {
        int r0 = f * 512 + qbase + m * 16 + (lane >> 2);
        #pragma unroll
        for (int nt = 0; nt < 4; nt++) {
            int col = n32 + nt * 8 + (lane & 3) * 2;
            float a0 = O[m][nt][0] * inv[m][0], a1 = O[m][nt][1] * inv[m][0];
            float a2 = O[m][nt][2] * inv[m][1], a3 = O[m][nt][3] * inv[m][1];
            *(uint32_t*)(g_obh + (size_t)r0 * 512 + col)       = bfpack_hi(a0, a1);
            *(uint32_t*)(g_obl + (size_t)r0 * 512 + col)       = bfpack_lo(a0, a1);
            *(uint32_t*)(g_obh + (size_t)(r0 + 8) * 512 + col) = bfpack_hi(a2, a3);
            *(uint32_t*)(g_obl + (size_t)(r0 + 8) * 512 + col) = bfpack_lo(a2, a3);
        }
    }
}

// ---------------- launcher ----------------
extern "C" void kernel_launch(void* const* d_in, const int* in_sizes, int n_in,
                              void* d_out, int out_size)
{
    const float* hidden = (const float*)d_in[0];
    const float* W      = (const float*)d_in[1];
    const float* bias   = (const float*)d_in[2];
    const float* Wo     = (const float*)d_in[3];
    const float* bo     = (const float*)d_in[4];
    const float* te     = (const float*)d_in[5];
    float* out = (float*)d_out;

    float *p_qkv, *p_qh, *p_kp, *p_vp;
    __nv_bfloat16 *p_hh, *p_hl, *p_Wh, *p_Wl, *p_Woh, *p_Wol;
    __nv_bfloat16 *p_qbh, *p_qbl, *p_kbh, *p_kbl, *p_vbh, *p_vbl, *p_obh, *p_obl;
    cudaGetSymbolAddress((void**)&p_qkv, g_qkv);
    cudaGetSymbolAddress((void**)&p_qh,  g_qh);
    cudaGetSymbolAddress((void**)&p_kp,  g_kp);
    cudaGetSymbolAddress((void**)&p_vp,  g_vp);
    cudaGetSymbolAddress((void**)&p_hh,  g_hh);   cudaGetSymbolAddress((void**)&p_hl,  g_hl);
    cudaGetSymbolAddress((void**)&p_Wh,  g_Wh);   cudaGetSymbolAddress((void**)&p_Wl,  g_Wl);
    cudaGetSymbolAddress((void**)&p_Woh, g_Woh);  cudaGetSymbolAddress((void**)&p_Wol, g_Wol);
    cudaGetSymbolAddress((void**)&p_qbh, g_qbh);  cudaGetSymbolAddress((void**)&p_qbl, g_qbl);
    cudaGetSymbolAddress((void**)&p_kbh, g_kbh);  cudaGetSymbolAddress((void**)&p_kbl, g_kbl);
    cudaGetSymbolAddress((void**)&p_vbh, g_vbh);  cudaGetSymbolAddress((void**)&p_vbl, g_vbl);
    cudaGetSymbolAddress((void**)&p_obh, g_obh);  cudaGetSymbolAddress((void**)&p_obl, g_obl);

    // 0) split inputs into bf16 hi/lo
    split_bf16<<<8192 * 512 / 1024, 256>>>(hidden, p_hh, p_hl);
    split_bf16<<<1536 * 512 / 1024, 256>>>(W, p_Wh, p_Wl);
    split_bf16<<< 512 * 512 / 1024, 256>>>(Wo, p_Woh, p_Wol);

    // 1) qkv = hidden @ in_proj_W^T + b
    gemm_wmma<<<dim3(12, 64), 256>>>(p_hh, p_hl, p_Wh, p_Wl, bias, p_qkv, 1536, 0);

    // 2) RoPE + stream reorder
    rope_reorder<<<8192, 256>>>(p_qkv);

    // 3) pad frames of kproj/vproj = bias
    fill_pad<<<(2 * 3 * 512 * 512) / 256, 256>>>(bias);

    // 4) teK = temporal_embed @ Wk^T
    compute_teK<<<dim3(4, 4), 128>>>(te, W);

    // 5-7) second projections
    gemm_wmma<<<dim3(4, 64), 256>>>(p_qbh, p_qbl, p_Wh, p_Wl, bias, p_qh, 512, 0);
    gemm_wmma<<<dim3(4, 64), 256>>>(p_kbh, p_kbl, p_Wh + 512 * 512, p_Wl + 512 * 512,
                                    bias + 512, p_kp, 512, 1);
    gemm_wmma<<<dim3(4, 64), 256>>>(p_vbh, p_vbl, p_Wh + 1024 * 512, p_Wl + 1024 * 512,
                                    bias + 1024, p_vp, 512, 1);

    // 8) sliding-window attention on tensor cores
    attn_mma<<<dim3(2, 16, 16), 256>>>();

    // 9) out = o @ Wo^T + bo
    gemm_wmma<<<dim3(4, 64), 256>>>(p_obh, p_obl, p_Woh, p_Wol, bo, out, 512, 0);
}

// round 6
// speedup vs baseline: 2.4266x; 1.1024x over previous
#include <cuda_runtime.h>
#include <cuda_bf16.h>
#include <mma.h>
#include <math.h>
#include <cstdint>

using namespace nvcuda;

// ---------------- problem constants ----------------
// B=2, T=8, H=16, W=16, E=512, n_heads=16, d=32, S=4096, L2=512, WINDOW=4
// frames BT=16, padded frames per batch TPAD=11, K of all GEMMs = 512

// ---------------- device scratch ----------------
__device__ __align__(128) float g_qkv[8192ull * 1536];        // fp32 qkv
__device__ __align__(128) float g_teK[4 * 512];

// bf16 hi/lo split operands
__device__ __align__(128) __nv_bfloat16 g_hh [8192ull * 512], g_hl [8192ull * 512]; // hidden
__device__ __align__(128) __nv_bfloat16 g_Wh [1536ull * 512], g_Wl [1536ull * 512]; // in_proj W
__device__ __align__(128) __nv_bfloat16 g_Woh[ 512ull * 512], g_Wol[ 512ull * 512]; // out_proj W
__device__ __align__(128) __nv_bfloat16 g_qbh[8192ull * 512], g_qbl[8192ull * 512]; // roped q
__device__ __align__(128) __nv_bfloat16 g_kbh[8192ull * 512], g_kbl[8192ull * 512]; // roped k
__device__ __align__(128) __nv_bfloat16 g_vbh[8192ull * 512], g_vbl[8192ull * 512]; // v
__device__ __align__(128) __nv_bfloat16 g_obh[8192ull * 512], g_obl[8192ull * 512]; // attn out

// attention operands, precomputed split
__device__ __align__(128) __nv_bfloat16 g_qwh[8192ull * 512], g_qwl[8192ull * 512];   // scaled q
__device__ __align__(128) __nv_bfloat16 g_kwh[2ull*8*4*512*512], g_kwl[2ull*8*4*512*512]; // windowed k (+teK)
__device__ __align__(128) __nv_bfloat16 g_vph[2ull*11*512*512],  g_vpl[2ull*11*512*512];  // padded v

// ---------------- helpers ----------------
__device__ __forceinline__ void split2(float x, float y,
                                       __nv_bfloat162& h, __nv_bfloat162& l) {
    __nv_bfloat16 hx = __float2bfloat16_rn(x);
    __nv_bfloat16 hy = __float2bfloat16_rn(y);
    h = __halves2bfloat162(hx, hy);
    l = __halves2bfloat162(__float2bfloat16_rn(x - __bfloat162float(hx)),
                           __float2bfloat16_rn(y - __bfloat162float(hy)));
}

__device__ __forceinline__ uint32_t bfpack_hi(float x, float y) {
    __nv_bfloat162 h = __floats2bfloat162_rn(x, y);
    return *(uint32_t*)&h;
}
__device__ __forceinline__ uint32_t bfpack_lo(float x, float y) {
    float rx = __bfloat162float(__float2bfloat16_rn(x));
    float ry = __bfloat162float(__float2bfloat16_rn(y));
    __nv_bfloat162 l = __floats2bfloat162_rn(x - rx, y - ry);
    return *(uint32_t*)&l;
}

__device__ __forceinline__ uint32_t smem_u32(const void* p) {
    uint32_t a;
    asm("{ .reg .u64 t; cvta.to.shared.u64 t, %1; cvt.u32.u64 %0, t; }" : "=r"(a) : "l"(p));
    return a;
}
__device__ __forceinline__ void ldsm_x2(uint32_t& r0, uint32_t& r1, uint32_t addr) {
    asm volatile("ldmatrix.sync.aligned.m8n8.x2.shared.b16 {%0,%1}, [%2];"
        : "=r"(r0), "=r"(r1) : "r"(addr));
}
__device__ __forceinline__ void ldsm_x2t(uint32_t& r0, uint32_t& r1, uint32_t addr) {
    asm volatile("ldmatrix.sync.aligned.m8n8.x2.trans.shared.b16 {%0,%1}, [%2];"
        : "=r"(r0), "=r"(r1) : "r"(addr));
}
__device__ __forceinline__ void mma16816(float* d, const uint32_t* a, uint32_t b0, uint32_t b1) {
    asm volatile("mma.sync.aligned.m16n8k16.row.col.f32.bf16.bf16.f32 "
        "{%0,%1,%2,%3}, {%4,%5,%6,%7}, {%8,%9}, {%0,%1,%2,%3};"
        : "+f"(d[0]), "+f"(d[1]), "+f"(d[2]), "+f"(d[3])
        : "r"(a[0]), "r"(a[1]), "r"(a[2]), "r"(a[3]), "r"(b0), "r"(b1));
}
__device__ __forceinline__ void cp16(uint32_t dst, const void* src) {
    asm volatile("cp.async.cg.shared.global [%0], [%1], 16;" :: "r"(dst), "l"(src));
}

// ---------------- elementwise bf16 split ----------------
__global__ void split_bf16(const float* __restrict__ src,
                           __nv_bfloat16* __restrict__ hi, __nv_bfloat16* __restrict__ lo)
{
    size_t i = ((size_t)blockIdx.x * 256 + threadIdx.x) * 4;
    float4 v = *(const float4*)(src + i);
    __nv_bfloat162 h0, l0, h1, l1;
    split2(v.x, v.y, h0, l0);
    split2(v.z, v.w, h1, l1);
    *(__nv_bfloat162*)(hi + i)     = h0;
    *(__nv_bfloat162*)(hi + i + 2) = h1;
    *(__nv_bfloat162*)(lo + i)     = l0;
    *(__nv_bfloat162*)(lo + i + 2) = l1;
}

// ---------------- shared GEMM mainloop (macro-style via inline) ----------------
// computes 128x128 C tile (8 warps, 64x32 warp tiles), 3-pass bf16 split, leaves
// fc[][] accumulators; caller provides epilogue.
#define GEMM_MAINLOOP(Ahi, Alo, Bhi, Blo)                                           \
    wmma::fragment<wmma::accumulator, 16, 16, 16, float> fc[4][2];                  \
    _Pragma("unroll") for (int i = 0; i < 4; i++)                                   \
        _Pragma("unroll") for (int j = 0; j < 2; j++) wmma::fill_fragment(fc[i][j], 0.f); \
    uint4 rah0, rah1, ral0, ral1, rbh0, rbh1, rbl0, rbl1;                           \
    auto LD = [&](int k0) {                                                         \
        rah0 = *(const uint4*)(Ahi + aoff + k0); rah1 = *(const uint4*)(Ahi + aoff + k0 + 8); \
        ral0 = *(const uint4*)(Alo + aoff + k0); ral1 = *(const uint4*)(Alo + aoff + k0 + 8); \
        rbh0 = *(const uint4*)(Bhi + boff + k0); rbh1 = *(const uint4*)(Bhi + boff + k0 + 8); \
        rbl0 = *(const uint4*)(Blo + boff + k0); rbl1 = *(const uint4*)(Blo + boff + k0 + 8); \
    };                                                                              \
    LD(0);                                                                          \
    for (int k0 = 0; k0 < 512; k0 += 32) {                                          \
        *(uint4*)&sAh[soff] = rah0; *(uint4*)&sAh[soff + 8] = rah1;                 \
        *(uint4*)&sAl[soff] = ral0; *(uint4*)&sAl[soff + 8] = ral1;                 \
        *(uint4*)&sBh[soff] = rbh0; *(uint4*)&sBh[soff + 8] = rbh1;                 \
        *(uint4*)&sBl[soff] = rbl0; *(uint4*)&sBl[soff + 8] = rbl1;                 \
        __syncthreads();                                                            \
        if (k0 + 32 < 512) LD(k0 + 32);                                             \
        _Pragma("unroll") for (int ks = 0; ks < 32; ks += 16) {                     \
            wmma::fragment<wmma::matrix_a, 16, 16, 16, __nv_bfloat16, wmma::row_major> fah[4], fal[4]; \
            wmma::fragment<wmma::matrix_b, 16, 16, 16, __nv_bfloat16, wmma::col_major> fbh[2], fbl[2]; \
            _Pragma("unroll") for (int i = 0; i < 4; i++) {                         \
                wmma::load_matrix_sync(fah[i], &sAh[(wm + i * 16) * 40 + ks], 40);  \
                wmma::load_matrix_sync(fal[i], &sAl[(wm + i * 16) * 40 + ks], 40);  \
            }                                                                       \
            _Pragma("unroll") for (int j = 0; j < 2; j++) {                         \
                wmma::load_matrix_sync(fbh[j], &sBh[(wn + j * 16) * 40 + ks], 40);  \
                wmma::load_matrix_sync(fbl[j], &sBl[(wn + j * 16) * 40 + ks], 40);  \
            }                                                                       \
            _Pragma("unroll") for (int i = 0; i < 4; i++)                           \
                _Pragma("unroll") for (int j = 0; j < 2; j++) {                     \
                    wmma::mma_sync(fc[i][j], fah[i], fbh[j], fc[i][j]);             \
                    wmma::mma_sync(fc[i][j], fah[i], fbl[j], fc[i][j]);             \
                    wmma::mma_sync(fc[i][j], fal[i], fbh[j], fc[i][j]);             \
                }                                                                   \
        }                                                                           \
        __syncthreads();                                                            \
    }

// ---------------- GEMM with fp32 output (big qkv GEMM + out-proj) ----------------
__global__ void __launch_bounds__(256) gemm_wmma(
    const __nv_bfloat16* __restrict__ Ahi, const __nv_bfloat16* __restrict__ Alo,
    const __nv_bfloat16* __restrict__ Bhi, const __nv_bfloat16* __restrict__ Blo,
    const float* __restrict__ bias, float* __restrict__ C, int N)
{
    __shared__ __align__(16) __nv_bfloat16 sAh[128 * 40], sAl[128 * 40];
    __shared__ __align__(16) __nv_bfloat16 sBh[128 * 40], sBl[128 * 40];
    const int tid = threadIdx.x, w = tid >> 5, lane = tid & 31;
    const int m0 = blockIdx.y * 128, n0 = blockIdx.x * 128;
    const int wm = (w >> 2) * 64, wn = (w & 3) * 32;
    const int lrow = tid >> 1, lcol = (tid & 1) * 16;
    const size_t aoff = (size_t)(m0 + lrow) * 512 + lcol;
    const size_t boff = (size_t)(n0 + lrow) * 512 + lcol;
    const int soff = lrow * 40 + lcol;

    GEMM_MAINLOOP(Ahi, Alo, Bhi, Blo)

    float* cst = reinterpret_cast<float*>(sAh) + w * 256;
    const int er = lane >> 1, ec = (lane & 1) * 8;
    #pragma unroll
    for (int i = 0; i < 4; i++)
        #pragma unroll
        for (int j = 0; j < 2; j++) {
            wmma::store_matrix_sync(cst, fc[i][j], 16, wmma::mem_row_major);
            __syncwarp();
            int gr = m0 + wm + i * 16 + er;
            int gn = n0 + wn + j * 16 + ec;
            float4 v0 = *(float4*)&cst[er * 16 + ec];
            float4 v1 = *(float4*)&cst[er * 16 + ec + 4];
            float4 b0 = *(const float4*)(bias + gn);
            float4 b1 = *(const float4*)(bias + gn + 4);
            v0.x += b0.x; v0.y += b0.y; v0.z += b0.z; v0.w += b0.w;
            v1.x += b1.x; v1.y += b1.y; v1.z += b1.z; v1.w += b1.w;
            float* crow = C + (size_t)gr * N + gn;
            *(float4*)crow = v0;
            *(float4*)(crow + 4) = v1;
            __syncwarp();
        }
}

// ---------------- fused second projections (z = 0:q, 1:k-window, 2:v-padded) ----------------
__global__ void __launch_bounds__(256) gemm_small(
    const __nv_bfloat16* __restrict__ qAh, const __nv_bfloat16* __restrict__ qAl,
    const __nv_bfloat16* __restrict__ kAh, const __nv_bfloat16* __restrict__ kAl,
    const __nv_bfloat16* __restrict__ vAh, const __nv_bfloat16* __restrict__ vAl,
    const __nv_bfloat16* __restrict__ Wh,  const __nv_bfloat16* __restrict__ Wl,
    const float* __restrict__ bias_all)
{
    __shared__ __align__(16) __nv_bfloat16 sAh[128 * 40], sAl[128 * 40];
    __shared__ __align__(16) __nv_bfloat16 sBh[128 * 40], sBl[128 * 40];
    const int tid = threadIdx.x, w = tid >> 5, lane = tid & 31;
    const int z = blockIdx.z;
    const int m0 = blockIdx.y * 128, n0 = blockIdx.x * 128;
    const int wm = (w >> 2) * 64, wn = (w & 3) * 32;
    const int lrow = tid >> 1, lcol = (tid & 1) * 16;
    const size_t aoff = (size_t)(m0 + lrow) * 512 + lcol;
    const size_t boff = (size_t)(n0 + lrow) * 512 + lcol;
    const int soff = lrow * 40 + lcol;

    const __nv_bfloat16* Ahi = (z == 0) ? qAh : (z == 1) ? kAh : vAh;
    const __nv_bfloat16* Alo = (z == 0) ? qAl : (z == 1) ? kAl : vAl;
    const __nv_bfloat16* Bhi = Wh + (size_t)z * 512 * 512;
    const __nv_bfloat16* Blo = Wl + (size_t)z * 512 * 512;
    const float* bias = bias_all + z * 512;

    GEMM_MAINLOOP(Ahi, Alo, Bhi, Blo)

    float* cst = reinterpret_cast<float*>(sAh) + w * 256;
    const int er = lane >> 1, ec = (lane & 1) * 8;
    const float scale = 0.17677669529663689f;  // 1/sqrt(32)
    #pragma unroll
    for (int i = 0; i < 4; i++)
        #pragma unroll
        for (int j = 0; j < 2; j++) {
            wmma::store_matrix_sync(cst, fc[i][j], 16, wmma::mem_row_major);
            __syncwarp();
            int gr = m0 + wm + i * 16 + er;
            int gn = n0 + wn + j * 16 + ec;
            float v[8];
            #pragma unroll
            for (int c = 0; c < 8; c++) v[c] = cst[er * 16 + ec + c] + bias[gn + c];

            if (z == 0) {
                // q: scale + split
                size_t o = (size_t)gr * 512 + gn;
                #pragma unroll
                for (int c = 0; c < 8; c += 2) {
                    __nv_bfloat162 h, l;
                    split2(v[c] * scale, v[c + 1] * scale, h, l);
                    *(__nv_bfloat162*)(g_qwh + o + c) = h;
                    *(__nv_bfloat162*)(g_qwl + o + c) = l;
                }
            } else if (z == 1) {
                // k: emit windowed variants with teK added
                int b = gr >> 12, f = (gr >> 9) & 7, l = gr & 511;
                #pragma unroll
                for (int ii = 0; ii < 4; ii++) {
                    int t = f + 3 - ii;
                    if ((unsigned)t < 8u) {
                        size_t o = ((size_t)((b * 8 + t) * 4 + ii) * 512 + l) * 512 + gn;
                        const float* tek = g_teK + ii * 512 + gn;
                        #pragma unroll
                        for (int c = 0; c < 8; c += 2) {
                            __nv_bfloat162 h, lo2;
                            split2(v[c] + tek[c], v[c + 1] + tek[c + 1], h, lo2);
                            *(__nv_bfloat162*)(g_kwh + o + c) = h;
                            *(__nv_bfloat162*)(g_kwl + o + c) = lo2;
                        }
                    }
                }
            } else {
                // v: padded layout
                int out_r = gr + ((gr >> 12) + 1) * 1536;
                size_t o = (size_t)out_r * 512 + gn;
                #pragma unroll
                for (int c = 0; c < 8; c += 2) {
                    __nv_bfloat162 h, l;
                    split2(v[c], v[c + 1], h, l);
                    *(__nv_bfloat162*)(g_vph + o + c) = h;
                    *(__nv_bfloat162*)(g_vpl + o + c) = l;
                }
            }
            __syncwarp();
        }
}

// ---------------- RoPE + stream reorder (emits bf16 hi/lo) ----------------
__global__ void rope_reorder(const float* __restrict__ qkv)
{
    int token = blockIdx.x;
    int b = token >> 12;
    int s = token & 4095;
    int p = threadIdx.x;
    int j = p & 15;

    int tqk, lqk, fidx;
    float pos;
    if (s < 2048) {
        tqk = s >> 8; lqk = s & 255;
        fidx = j; pos = (float)lqk;
    } else {
        int s2 = s - 2048;
        tqk = s2 >> 8;
        int pp = s2 & 255;
        lqk = 256 + pp;
        int h = pp >> 4, w = pp & 15;
        if (j < 8) { fidx = 2 * j;           pos = (float)h; }
        else       { fidx = 2 * (j - 8) + 1; pos = (float)w; }
    }
    float freq = __powf(10000.0f, -(float)fidx * (1.0f / 16.0f));
    float ang = pos * freq;
    float sn, cs;
    sincosf(ang, &sn, &cs);

    const float* row = qkv + (size_t)token * 1536;
    int frame = b * 8 + tqk;
    size_t ob = ((size_t)frame * 512 + lqk) * 512 + 2 * p;

    __nv_bfloat162 h2, l2;
    float2 qv = *(const float2*)(row + 2 * p);
    split2(qv.x * cs - qv.y * sn, qv.x * sn + qv.y * cs, h2, l2);
    *(__nv_bfloat162*)(g_qbh + ob) = h2;
    *(__nv_bfloat162*)(g_qbl + ob) = l2;

    float2 kv = *(const float2*)(row + 512 + 2 * p);
    split2(kv.x * cs - kv.y * sn, kv.x * sn + kv.y * cs, h2, l2);
    *(__nv_bfloat162*)(g_kbh + ob) = h2;
    *(__nv_bfloat162*)(g_kbl + ob) = l2;

    float2 vv = *(const float2*)(row + 1024 + 2 * p);
    size_t vb = ((size_t)(b * 8 + (s >> 9)) * 512 + (s & 511)) * 512 + 2 * p;
    split2(vv.x, vv.y, h2, l2);
    *(__nv_bfloat162*)(g_vbh + vb) = h2;
    *(__nv_bfloat162*)(g_vbl + vb) = l2;
}

// ---------------- pad fills: k-window pads (bias_k + teK) and v pads (bias_v) ----------------
__global__ void fill_pad2(const float* __restrict__ bias)
{
    int rid = blockIdx.x;
    int e = threadIdx.x * 2;
    if (rid < 6144) {
        // k-window pad rows: (b, pair, l); pairs (t,i) with t+i<=2
        int b = rid / 3072;
        int rem = rid - b * 3072;
        int pr = rem >> 9, l = rem & 511;
        const int tt[6] = {0, 0, 1, 0, 1, 2};
        const int ii[6] = {0, 1, 0, 2, 1, 0};
        int t = tt[pr], i = ii[pr];
        float x = bias[512 + e]     + g_teK[i * 512 + e];
        float y = bias[512 + e + 1] + g_teK[i * 512 + e + 1];
        __nv_bfloat162 h, lo2;
        split2(x, y, h, lo2);
        size_t o = ((size_t)((b * 8 + t) * 4 + i) * 512 + l) * 512 + e;
        *(__nv_bfloat162*)(g_kwh + o) = h;
        *(__nv_bfloat162*)(g_kwl + o) = lo2;
    } else {
        int rid2 = rid - 6144;
        int b = rid2 / 1536;
        int rem = rid2 - b * 1536;
        int fp = rem >> 9, l = rem & 511;
        __nv_bfloat162 h, lo2;
        split2(bias[1024 + e], bias[1024 + e + 1], h, lo2);
        size_t o = ((size_t)(b * 11 + fp) * 512 + l) * 512 + e;
        *(__nv_bfloat162*)(g_vph + o) = h;
        *(__nv_bfloat162*)(g_vpl + o) = lo2;
    }
}

// ---------------- teK[i][e] = temporal_embed[i] . Wk[e] ----------------
__global__ void compute_teK(const float* __restrict__ te, const float* __restrict__ W)
{
    int i = blockIdx.y;
    int e = blockIdx.x * 128 + threadIdx.x;
    const float4* wk = (const float4*)(W + (size_t)(512 + e) * 512);
    const float4* tr = (const float4*)(te + i * 512);
    float s = 0.f;
    #pragma unroll 8
    for (int k = 0; k < 128; k++) {
        float4 a = tr[k], b = wk[k];
        s += a.x * b.x + a.y * b.y + a.z * b.z + a.w * b.w;
    }
    g_teK[i * 512 + e] = s;
}

// ---------------- tensor-core flash attention, cp.async pipelined ----------------
// grid (2, 16 heads, 16 frames), 256 threads = 8 warps; warp owns 32 q-rows.
// All operands precomputed bf16 hi/lo in gmem; inner loop = cp.async + ldsm + mma + exp.
__global__ void __launch_bounds__(256) attn_mma()
{
    const int f = blockIdx.z, head = blockIdx.y;
    const int tid = threadIdx.x, w = tid >> 5, lane = tid & 31;
    const int b = f >> 3, t = f & 7;
    const int n32 = head * 32;
    const int qbase = blockIdx.x * 256 + w * 32;

    // [buf][arr: 0=Kh 1=Kl 2=Vh 3=Vl][32*40]
    __shared__ __align__(16) __nv_bfloat16 sKV[2][4][32 * 40];

    // ---- Q fragments loaded directly from gmem (m16n8k16 A layout) ----
    uint32_t Qh[2][2][4], Ql[2][2][4];
    {
        int r = lane >> 2, c = (lane & 3) * 2;
        #pragma unroll
        for (int mt = 0; mt < 2; mt++)
            #pragma unroll
            for (int kt = 0; kt < 2; kt++) {
                size_t base = (size_t)(f * 512 + qbase + mt * 16 + r) * 512 + n32 + kt * 16 + c;
                Qh[mt][kt][0] = *(const uint32_t*)(g_qwh + base);
                Qh[mt][kt][1] = *(const uint32_t*)(g_qwh + base + 8 * 512);
                Qh[mt][kt][2] = *(const uint32_t*)(g_qwh + base + 8);
                Qh[mt][kt][3] = *(const uint32_t*)(g_qwh + base + 8 * 512 + 8);
                Ql[mt][kt][0] = *(const uint32_t*)(g_qwl + base);
                Ql[mt][kt][1] = *(const uint32_t*)(g_qwl + base + 8 * 512);
                Ql[mt][kt][2] = *(const uint32_t*)(g_qwl + base + 8);
                Ql[mt][kt][3] = *(const uint32_t*)(g_qwl + base + 8 * 512 + 8);
            }
    }

    float O[2][4][4];
    float lsum[2][2] = {{0.f, 0.f}, {0.f, 0.f}};
    #pragma unroll
    for (int m = 0; m < 2; m++)
        #pragma unroll
        for (int n = 0; n < 4; n++)
            #pragma unroll
            for (int c = 0; c < 4; c++) O[m][n][c] = 0.f;

    // per-thread staging map: 2 cp.async of 16B each
    const int idx0 = tid * 2;
    const int arr0 = idx0 >> 7;
    const int r0s = (idx0 >> 2) & 31, seg0 = idx0 & 3;
    const int r1s = ((idx0 + 1) >> 2) & 31, seg1 = (idx0 + 1) & 3;

    auto stage = [&](int cc, int buf) {
        int slot = cc >> 4, lb = (cc & 15) << 5;
        size_t krow = (size_t)((b * 8 + t) * 4 + slot) * 512 + lb;
        size_t vrow = (size_t)(b * 11 + t + slot) * 512 + lb;
        const __nv_bfloat16* base =
            (arr0 == 0) ? g_kwh + (krow * 512 + n32) :
            (arr0 == 1) ? g_kwl + (krow * 512 + n32) :
            (arr0 == 2) ? g_vph + (vrow * 512 + n32) :
                          g_vpl + (vrow * 512 + n32);
        cp16(smem_u32(&sKV[buf][arr0][r0s * 40 + seg0 * 8]), base + (size_t)r0s * 512 + seg0 * 8);
        cp16(smem_u32(&sKV[buf][arr0][r1s * 40 + seg1 * 8]), base + (size_t)r1s * 512 + seg1 * 8);
        asm volatile("cp.async.commit_group;" ::: "memory");
    };

    stage(0, 0);

    for (int cc = 0; cc < 64; cc++) {
        asm volatile("cp.async.wait_group 0;" ::: "memory");
        __syncthreads();
        if (cc < 63) stage(cc + 1, (cc + 1) & 1);
        const int buf = cc & 1;

        // ---- S = Q @ K^T (3-pass split) ----
        float S[2][4][4];
        #pragma unroll
        for (int m = 0; m < 2; m++)
            #pragma unroll
            for (int n = 0; n < 4; n++)
                #pragma unroll
                for (int c = 0; c < 4; c++) S[m][n][c] = 0.f;

        #pragma unroll
        for (int kt = 0; kt < 2; kt++) {
            #pragma unroll
            for (int nt = 0; nt < 4; nt++) {
                int l = lane & 15;
                int ki = (nt * 8 + (l & 7)) * 40 + kt * 16 + (l >> 3) * 8;
                uint32_t kh0, kh1, kl0, kl1;
                ldsm_x2(kh0, kh1, smem_u32(&sKV[buf][0][ki]));
                ldsm_x2(kl0, kl1, smem_u32(&sKV[buf][1][ki]));
                #pragma unroll
                for (int m = 0; m < 2; m++) {
                    mma16816(S[m][nt], Qh[m][kt], kh0, kh1);
                    mma16816(S[m][nt], Qh[m][kt], kl0, kl1);
                    mma16816(S[m][nt], Ql[m][kt], kh0, kh1);
                }
            }
        }

        // ---- exp + lsum (registers) ----
        #pragma unroll
        for (int m = 0; m < 2; m++)
            #pragma unroll
            for (int n = 0; n < 4; n++) {
                S[m][n][0] = __expf(S[m][n][0]);
                S[m][n][1] = __expf(S[m][n][1]);
                S[m][n][2] = __expf(S[m][n][2]);
                S[m][n][3] = __expf(S[m][n][3]);
                lsum[m][0] += S[m][n][0] + S[m][n][1];
                lsum[m][1] += S[m][n][2] + S[m][n][3];
            }

        // ---- O += P @ V (3-pass split) ----
        #pragma unroll
        for (int kt = 0; kt < 2; kt++) {
            uint32_t Ph[2][4], Pl[2][4];
            #pragma unroll
            for (int m = 0; m < 2; m++) {
                const float* s0 = S[m][2 * kt];
                const float* s1 = S[m][2 * kt + 1];
                Ph[m][0] = bfpack_hi(s0[0], s0[1]); Pl[m][0] = bfpack_lo(s0[0], s0[1]);
                Ph[m][1] = bfpack_hi(s0[2], s0[3]); Pl[m][1] = bfpack_lo(s0[2], s0[3]);
                Ph[m][2] = bfpack_hi(s1[0], s1[1]); Pl[m][2] = bfpack_lo(s1[0], s1[1]);
                Ph[m][3] = bfpack_hi(s1[2], s1[3]); Pl[m][3] = bfpack_lo(s1[2], s1[3]);
            }
            #pragma unroll
            for (int nt = 0; nt < 4; nt++) {
                int l = lane & 15;
                int vi = (kt * 16 + l) * 40 + nt * 8;
                uint32_t vh0, vh1, vl0, vl1;
                ldsm_x2t(vh0, vh1, smem_u32(&sKV[buf][2][vi]));
                ldsm_x2t(vl0, vl1, smem_u32(&sKV[buf][3][vi]));
                #pragma unroll
                for (int m = 0; m < 2; m++) {
                    mma16816(O[m][nt], Ph[m], vh0, vh1);
                    mma16816(O[m][nt], Ph[m], vl0, vl1);
                    mma16816(O[m][nt], Pl[m], vh0, vh1);
                }
            }
        }
    }

    // ---- epilogue: normalize + write bf16 hi/lo ----
    float inv[2][2];
    #pragma unroll
    for (int m = 0; m < 2; m++)
        #pragma unroll
        for (int h = 0; h < 2; h++) {
            float s = lsum[m][h];
            s += __shfl_xor_sync(0xffffffffu, s, 1);
            s += __shfl_xor_sync(0xffffffffu, s, 2);
            inv[m][h] = 1.f / s;
        }
    #pragma unroll
    for (int m = 0; m < 2; m++) {
        int r0 = f * 512 + qbase + m * 16 + (lane >> 2);
        #pragma unroll
        for (int nt = 0; nt < 4; nt++) {
            int col = n32 + nt * 8 + (lane & 3) * 2;
            float a0 = O[m][nt][0] * inv[m][0], a1 = O[m][nt][1] * inv[m][0];
            float a2 = O[m][nt][2] * inv[m][1], a3 = O[m][nt][3] * inv[m][1];
            *(uint32_t*)(g_obh + (size_t)r0 * 512 + col)       = bfpack_hi(a0, a1);
            *(uint32_t*)(g_obl + (size_t)r0 * 512 + col)       = bfpack_lo(a0, a1);
            *(uint32_t*)(g_obh + (size_t)(r0 + 8) * 512 + col) = bfpack_hi(a2, a3);
            *(uint32_t*)(g_obl + (size_t)(r0 + 8) * 512 + col) = bfpack_lo(a2, a3);
        }
    }
}

// ---------------- launcher ----------------
extern "C" void kernel_launch(void* const* d_in, const int* in_sizes, int n_in,
                              void* d_out, int out_size)
{
    const float* hidden = (const float*)d_in[0];
    const float* W      = (const float*)d_in[1];
    const float* bias   = (const float*)d_in[2];
    const float* Wo     = (const float*)d_in[3];
    const float* bo     = (const float*)d_in[4];
    const float* te     = (const float*)d_in[5];
    float* out = (float*)d_out;

    float* p_qkv;
    __nv_bfloat16 *p_hh, *p_hl, *p_Wh, *p_Wl, *p_Woh, *p_Wol;
    __nv_bfloat16 *p_qbh, *p_qbl, *p_kbh, *p_kbl, *p_vbh, *p_vbl, *p_obh, *p_obl;
    cudaGetSymbolAddress((void**)&p_qkv, g_qkv);
    cudaGetSymbolAddress((void**)&p_hh,  g_hh);   cudaGetSymbolAddress((void**)&p_hl,  g_hl);
    cudaGetSymbolAddress((void**)&p_Wh,  g_Wh);   cudaGetSymbolAddress((void**)&p_Wl,  g_Wl);
    cudaGetSymbolAddress((void**)&p_Woh, g_Woh);  cudaGetSymbolAddress((void**)&p_Wol, g_Wol);
    cudaGetSymbolAddress((void**)&p_qbh, g_qbh);  cudaGetSymbolAddress((void**)&p_qbl, g_qbl);
    cudaGetSymbolAddress((void**)&p_kbh, g_kbh);  cudaGetSymbolAddress((void**)&p_kbl, g_kbl);
    cudaGetSymbolAddress((void**)&p_vbh, g_vbh);  cudaGetSymbolAddress((void**)&p_vbl, g_vbl);
    cudaGetSymbolAddress((void**)&p_obh, g_obh);  cudaGetSymbolAddress((void**)&p_obl, g_obl);

    // 0) split fp32 inputs into bf16 hi/lo
    split_bf16<<<8192 * 512 / 1024, 256>>>(hidden, p_hh, p_hl);
    split_bf16<<<1536 * 512 / 1024, 256>>>(W, p_Wh, p_Wl);
    split_bf16<<< 512 * 512 / 1024, 256>>>(Wo, p_Woh, p_Wol);

    // 1) teK = temporal_embed @ Wk^T (needed by gemm_small z=1 and fill_pad2)
    compute_teK<<<dim3(4, 4), 128>>>(te, W);

    // 2) qkv = hidden @ in_proj_W^T + b
    gemm_wmma<<<dim3(12, 64), 256>>>(p_hh, p_hl, p_Wh, p_Wl, bias, p_qkv, 1536);

    // 3) RoPE + stream reorder (bf16 hi/lo q,k,v)
    rope_reorder<<<8192, 256>>>(p_qkv);

    // 4) pad fills for k-window and padded v
    fill_pad2<<<6144 + 3072, 256>>>(bias);

    // 5) fused second projections -> scaled-q / windowed-k(+teK) / padded-v, all bf16 hi/lo
    gemm_small<<<dim3(4, 64, 3), 256>>>(p_qbh, p_qbl, p_kbh, p_kbl, p_vbh, p_vbl,
                                        p_Wh, p_Wl, bias);

    // 6) sliding-window attention (cp.async pipelined, tensor cores)
    attn_mma<<<dim3(2, 16, 16), 256>>>();

    // 7) out = o @ Wo^T + bo
    gemm_wmma<<<dim3(4, 64), 256>>>(p_obh, p_obl, p_Woh, p_Wol, bo, out, 512);
}

// round 7
// speedup vs baseline: 3.1230x; 1.2870x over previous
#include <cuda_runtime.h>
#include <cuda_bf16.h>
#include <mma.h>
#include <math.h>
#include <cstdint>

using namespace nvcuda;

// ---------------- problem constants ----------------
// B=2, T=8, H=16, W=16, E=512, n_heads=16, d=32, S=4096, L2=512, WINDOW=4
// frames BT=16, padded frames per batch TPAD=11, K of all GEMMs = 512

// ---------------- device scratch ----------------
__device__ __align__(128) float g_qkv[8192ull * 1536];
__device__ __align__(128) float g_teK[4 * 512];

__device__ __align__(128) __nv_bfloat16 g_hh [8192ull * 512], g_hl [8192ull * 512];
__device__ __align__(128) __nv_bfloat16 g_Wh [1536ull * 512], g_Wl [1536ull * 512];
__device__ __align__(128) __nv_bfloat16 g_Woh[ 512ull * 512], g_Wol[ 512ull * 512];
__device__ __align__(128) __nv_bfloat16 g_qbh[8192ull * 512], g_qbl[8192ull * 512];
__device__ __align__(128) __nv_bfloat16 g_kbh[8192ull * 512], g_kbl[8192ull * 512];
__device__ __align__(128) __nv_bfloat16 g_vbh[8192ull * 512], g_vbl[8192ull * 512];
__device__ __align__(128) __nv_bfloat16 g_obh[8192ull * 512], g_obl[8192ull * 512];

// attention operands, precomputed split
__device__ __align__(128) __nv_bfloat16 g_qwh[8192ull * 512], g_qwl[8192ull * 512];
__device__ __align__(128) __nv_bfloat16 g_kwh[2ull*8*4*512*512], g_kwl[2ull*8*4*512*512];
__device__ __align__(128) __nv_bfloat16 g_vph[2ull*11*512*512],  g_vpl[2ull*11*512*512];

// ---------------- helpers ----------------
__device__ __forceinline__ void split2(float x, float y,
                                       __nv_bfloat162& h, __nv_bfloat162& l) {
    __nv_bfloat16 hx = __float2bfloat16_rn(x);
    __nv_bfloat16 hy = __float2bfloat16_rn(y);
    h = __halves2bfloat162(hx, hy);
    l = __halves2bfloat162(__float2bfloat16_rn(x - __bfloat162float(hx)),
                           __float2bfloat16_rn(y - __bfloat162float(hy)));
}
__device__ __forceinline__ uint32_t bfpack_hi(float x, float y) {
    __nv_bfloat162 h = __floats2bfloat162_rn(x, y);
    return *(uint32_t*)&h;
}
__device__ __forceinline__ uint32_t bfpack_lo(float x, float y) {
    float rx = __bfloat162float(__float2bfloat16_rn(x));
    float ry = __bfloat162float(__float2bfloat16_rn(y));
    __nv_bfloat162 l = __floats2bfloat162_rn(x - rx, y - ry);
    return *(uint32_t*)&l;
}
__device__ __forceinline__ uint32_t smem_u32(const void* p) {
    uint32_t a;
    asm("{ .reg .u64 t; cvta.to.shared.u64 t, %1; cvt.u32.u64 %0, t; }" : "=r"(a) : "l"(p));
    return a;
}
__device__ __forceinline__ void ldsm_x2(uint32_t& r0, uint32_t& r1, uint32_t addr) {
    asm volatile("ldmatrix.sync.aligned.m8n8.x2.shared.b16 {%0,%1}, [%2];"
        : "=r"(r0), "=r"(r1) : "r"(addr));
}
__device__ __forceinline__ void ldsm_x2t(uint32_t& r0, uint32_t& r1, uint32_t addr) {
    asm volatile("ldmatrix.sync.aligned.m8n8.x2.trans.shared.b16 {%0,%1}, [%2];"
        : "=r"(r0), "=r"(r1) : "r"(addr));
}
__device__ __forceinline__ void mma16816(float* d, const uint32_t* a, uint32_t b0, uint32_t b1) {
    asm volatile("mma.sync.aligned.m16n8k16.row.col.f32.bf16.bf16.f32 "
        "{%0,%1,%2,%3}, {%4,%5,%6,%7}, {%8,%9}, {%0,%1,%2,%3};"
        : "+f"(d[0]), "+f"(d[1]), "+f"(d[2]), "+f"(d[3])
        : "r"(a[0]), "r"(a[1]), "r"(a[2]), "r"(a[3]), "r"(b0), "r"(b1));
}
__device__ __forceinline__ void cp16(uint32_t dst, const void* src) {
    asm volatile("cp.async.cg.shared.global [%0], [%1], 16;" :: "r"(dst), "l"(src));
}
#define CP_COMMIT() asm volatile("cp.async.commit_group;" ::: "memory")
#define CP_WAIT0()  asm volatile("cp.async.wait_group 0;" ::: "memory")
#define CP_WAIT1()  asm volatile("cp.async.wait_group 1;" ::: "memory")

// ---------------- fused bf16 split of the 3 fp32 inputs ----------------
__global__ void split_all(const float* __restrict__ hidden, const float* __restrict__ W,
                          const float* __restrict__ Wo)
{
    int bid = blockIdx.x;
    const float* src;
    __nv_bfloat16 *hi, *lo;
    int rb;
    if (bid < 4096)      { src = hidden; hi = g_hh;  lo = g_hl;  rb = bid; }
    else if (bid < 4864) { src = W;      hi = g_Wh;  lo = g_Wl;  rb = bid - 4096; }
    else                 { src = Wo;     hi = g_Woh; lo = g_Wol; rb = bid - 4864; }
    size_t i = ((size_t)rb * 256 + threadIdx.x) * 4;
    float4 v = *(const float4*)(src + i);
    __nv_bfloat162 h0, l0, h1, l1;
    split2(v.x, v.y, h0, l0);
    split2(v.z, v.w, h1, l1);
    *(__nv_bfloat162*)(hi + i)     = h0;
    *(__nv_bfloat162*)(hi + i + 2) = h1;
    *(__nv_bfloat162*)(lo + i)     = l0;
    *(__nv_bfloat162*)(lo + i + 2) = l1;
}

// ---------------- cp.async double-buffered GEMM mainloop ----------------
// dynamic smem: 2 bufs x 4 arrays (Ah,Al,Bh,Bl) x 128x40 bf16 = 81920 B
// leaves fc[4][2] accumulators for the caller's epilogue.
#define GEMM_MAINLOOP(Ahi, Alo, Bhi, Blo)                                           \
    wmma::fragment<wmma::accumulator, 16, 16, 16, float> fc[4][2];                  \
    _Pragma("unroll") for (int i = 0; i < 4; i++)                                   \
        _Pragma("unroll") for (int j = 0; j < 2; j++) wmma::fill_fragment(fc[i][j], 0.f); \
    auto stage = [&](int st) {                                                      \
        int k0 = st * 32;                                                           \
        int bo = (st & 1) * 20480;                                                  \
        _Pragma("unroll") for (int i = 0; i < 8; i++) {                             \
            int c = tid + i * 256;                                                  \
            int arr = c >> 9, rem = c & 511, row = rem >> 2, seg = rem & 3;         \
            const __nv_bfloat16* src =                                              \
                (arr == 0) ? Ahi + (size_t)(m0 + row) * 512 + k0 + seg * 8 :        \
                (arr == 1) ? Alo + (size_t)(m0 + row) * 512 + k0 + seg * 8 :        \
                (arr == 2) ? Bhi + (size_t)(n0 + row) * 512 + k0 + seg * 8 :        \
                             Blo + (size_t)(n0 + row) * 512 + k0 + seg * 8;         \
            cp16(smem_u32(smp + bo + arr * 5120 + row * 40 + seg * 8), src);        \
        }                                                                           \
        CP_COMMIT();                                                                \
    };                                                                              \
    stage(0);                                                                       \
    for (int st = 0; st < 16; st++) {                                               \
        CP_WAIT0();                                                                 \
        __syncthreads();                                                            \
        if (st + 1 < 16) stage(st + 1);                                             \
        const __nv_bfloat16* sAh = smp + (st & 1) * 20480;                          \
        const __nv_bfloat16* sAl = sAh + 5120;                                      \
        const __nv_bfloat16* sBh = sAh + 10240;                                     \
        const __nv_bfloat16* sBl = sAh + 15360;                                     \
        _Pragma("unroll") for (int ks = 0; ks < 32; ks += 16) {                     \
            wmma::fragment<wmma::matrix_a, 16, 16, 16, __nv_bfloat16, wmma::row_major> fah[4], fal[4]; \
            wmma::fragment<wmma::matrix_b, 16, 16, 16, __nv_bfloat16, wmma::col_major> fbh[2], fbl[2]; \
            _Pragma("unroll") for (int i = 0; i < 4; i++) {                         \
                wmma::load_matrix_sync(fah[i], &sAh[(wm + i * 16) * 40 + ks], 40);  \
                wmma::load_matrix_sync(fal[i], &sAl[(wm + i * 16) * 40 + ks], 40);  \
            }                                                                       \
            _Pragma("unroll") for (int j = 0; j < 2; j++) {                         \
                wmma::load_matrix_sync(fbh[j], &sBh[(wn + j * 16) * 40 + ks], 40);  \
                wmma::load_matrix_sync(fbl[j], &sBl[(wn + j * 16) * 40 + ks], 40);  \
            }                                                                       \
            _Pragma("unroll") for (int i = 0; i < 4; i++)                           \
                _Pragma("unroll") for (int j = 0; j < 2; j++) {                     \
                    wmma::mma_sync(fc[i][j], fah[i], fbh[j], fc[i][j]);             \
                    wmma::mma_sync(fc[i][j], fah[i], fbl[j], fc[i][j]);             \
                    wmma::mma_sync(fc[i][j], fal[i], fbh[j], fc[i][j]);             \
                }                                                                   \
        }                                                                           \
        __syncthreads();                                                            \
    }

static constexpr int GEMM_SMEM = 2 * 4 * 5120 * 2;  // 81920 bytes

// ---------------- GEMM with fp32 output ----------------
__global__ void __launch_bounds__(256, 2) gemm_wmma(
    const __nv_bfloat16* __restrict__ Ahi, const __nv_bfloat16* __restrict__ Alo,
    const __nv_bfloat16* __restrict__ Bhi, const __nv_bfloat16* __restrict__ Blo,
    const float* __restrict__ bias, float* __restrict__ C, int N)
{
    extern __shared__ __align__(16) __nv_bfloat16 smp[];
    const int tid = threadIdx.x, w = tid >> 5, lane = tid & 31;
    const int m0 = blockIdx.y * 128, n0 = blockIdx.x * 128;
    const int wm = (w >> 2) * 64, wn = (w & 3) * 32;

    GEMM_MAINLOOP(Ahi, Alo, Bhi, Blo)

    float* cst = reinterpret_cast<float*>(smp) + w * 256;
    const int er = lane >> 1, ec = (lane & 1) * 8;
    #pragma unroll
    for (int i = 0; i < 4; i++)
        #pragma unroll
        for (int j = 0; j < 2; j++) {
            wmma::store_matrix_sync(cst, fc[i][j], 16, wmma::mem_row_major);
            __syncwarp();
            int gr = m0 + wm + i * 16 + er;
            int gn = n0 + wn + j * 16 + ec;
            float4 v0 = *(float4*)&cst[er * 16 + ec];
            float4 v1 = *(float4*)&cst[er * 16 + ec + 4];
            float4 b0 = *(const float4*)(bias + gn);
            float4 b1 = *(const float4*)(bias + gn + 4);
            v0.x += b0.x; v0.y += b0.y; v0.z += b0.z; v0.w += b0.w;
            v1.x += b1.x; v1.y += b1.y; v1.z += b1.z; v1.w += b1.w;
            float* crow = C + (size_t)gr * N + gn;
            *(float4*)crow = v0;
            *(float4*)(crow + 4) = v1;
            __syncwarp();
        }
}

// ---------------- fused second projections (z = 0:q, 1:k-window, 2:v-padded) ----------------
__global__ void __launch_bounds__(256, 2) gemm_small(
    const __nv_bfloat16* __restrict__ qAh, const __nv_bfloat16* __restrict__ qAl,
    const __nv_bfloat16* __restrict__ kAh, const __nv_bfloat16* __restrict__ kAl,
    const __nv_bfloat16* __restrict__ vAh, const __nv_bfloat16* __restrict__ vAl,
    const __nv_bfloat16* __restrict__ Wh,  const __nv_bfloat16* __restrict__ Wl,
    const float* __restrict__ bias_all)
{
    extern __shared__ __align__(16) __nv_bfloat16 smp[];
    const int tid = threadIdx.x, w = tid >> 5, lane = tid & 31;
    const int z = blockIdx.z;
    const int m0 = blockIdx.y * 128, n0 = blockIdx.x * 128;
    const int wm = (w >> 2) * 64, wn = (w & 3) * 32;

    const __nv_bfloat16* Ahi = (z == 0) ? qAh : (z == 1) ? kAh : vAh;
    const __nv_bfloat16* Alo = (z == 0) ? qAl : (z == 1) ? kAl : vAl;
    const __nv_bfloat16* Bhi = Wh + (size_t)z * 512 * 512;
    const __nv_bfloat16* Blo = Wl + (size_t)z * 512 * 512;
    const float* bias = bias_all + z * 512;

    GEMM_MAINLOOP(Ahi, Alo, Bhi, Blo)

    float* cst = reinterpret_cast<float*>(smp) + w * 256;
    const int er = lane >> 1, ec = (lane & 1) * 8;
    // q pre-scale folds 1/sqrt(d) AND log2(e) (attention uses exp2)
    const float scale = 0.17677669529663689f * 1.4426950408889634f;
    #pragma unroll
    for (int i = 0; i < 4; i++)
        #pragma unroll
        for (int j = 0; j < 2; j++) {
            wmma::store_matrix_sync(cst, fc[i][j], 16, wmma::mem_row_major);
            __syncwarp();
            int gr = m0 + wm + i * 16 + er;
            int gn = n0 + wn + j * 16 + ec;
            float v[8];
            #pragma unroll
            for (int c = 0; c < 8; c++) v[c] = cst[er * 16 + ec + c] + bias[gn + c];

            if (z == 0) {
                size_t o = (size_t)gr * 512 + gn;
                #pragma unroll
                for (int c = 0; c < 8; c += 2) {
                    __nv_bfloat162 h, l;
                    split2(v[c] * scale, v[c + 1] * scale, h, l);
                    *(__nv_bfloat162*)(g_qwh + o + c) = h;
                    *(__nv_bfloat162*)(g_qwl + o + c) = l;
                }
            } else if (z == 1) {
                int b = gr >> 12, f = (gr >> 9) & 7, l = gr & 511;
                #pragma unroll
                for (int ii = 0; ii < 4; ii++) {
                    int t = f + 3 - ii;
                    if ((unsigned)t < 8u) {
                        size_t o = ((size_t)((b * 8 + t) * 4 + ii) * 512 + l) * 512 + gn;
                        const float* tek = g_teK + ii * 512 + gn;
                        #pragma unroll
                        for (int c = 0; c < 8; c += 2) {
                            __nv_bfloat162 h, lo2;
                            split2(v[c] + tek[c], v[c + 1] + tek[c + 1], h, lo2);
                            *(__nv_bfloat162*)(g_kwh + o + c) = h;
                            *(__nv_bfloat162*)(g_kwl + o + c) = lo2;
                        }
                    }
                }
            } else {
                int out_r = gr + ((gr >> 12) + 1) * 1536;
                size_t o = (size_t)out_r * 512 + gn;
                #pragma unroll
                for (int c = 0; c < 8; c += 2) {
                    __nv_bfloat162 h, l;
                    split2(v[c], v[c + 1], h, l);
                    *(__nv_bfloat162*)(g_vph + o + c) = h;
                    *(__nv_bfloat162*)(g_vpl + o + c) = l;
                }
            }
            __syncwarp();
        }
}

// ---------------- RoPE + stream reorder ----------------
__global__ void rope_reorder(const float* __restrict__ qkv)
{
    int token = blockIdx.x;
    int b = token >> 12;
    int s = token & 4095;
    int p = threadIdx.x;
    int j = p & 15;

    int tqk, lqk, fidx;
    float pos;
    if (s < 2048) {
        tqk = s >> 8; lqk = s & 255;
        fidx = j; pos = (float)lqk;
    } else {
        int s2 = s - 2048;
        tqk = s2 >> 8;
        int pp = s2 & 255;
        lqk = 256 + pp;
        int h = pp >> 4, w = pp & 15;
        if (j < 8) { fidx = 2 * j;           pos = (float)h; }
        else       { fidx = 2 * (j - 8) + 1; pos = (float)w; }
    }
    float freq = __powf(10000.0f, -(float)fidx * (1.0f / 16.0f));
    float ang = pos * freq;
    float sn, cs;
    sincosf(ang, &sn, &cs);

    const float* row = qkv + (size_t)token * 1536;
    int frame = b * 8 + tqk;
    size_t ob = ((size_t)frame * 512 + lqk) * 512 + 2 * p;

    __nv_bfloat162 h2, l2;
    float2 qv = *(const float2*)(row + 2 * p);
    split2(qv.x * cs - qv.y * sn, qv.x * sn + qv.y * cs, h2, l2);
    *(__nv_bfloat162*)(g_qbh + ob) = h2;
    *(__nv_bfloat162*)(g_qbl + ob) = l2;

    float2 kv = *(const float2*)(row + 512 + 2 * p);
    split2(kv.x * cs - kv.y * sn, kv.x * sn + kv.y * cs, h2, l2);
    *(__nv_bfloat162*)(g_kbh + ob) = h2;
    *(__nv_bfloat162*)(g_kbl + ob) = l2;

    float2 vv = *(const float2*)(row + 1024 + 2 * p);
    size_t vb = ((size_t)(b * 8 + (s >> 9)) * 512 + (s & 511)) * 512 + 2 * p;
    split2(vv.x, vv.y, h2, l2);
    *(__nv_bfloat162*)(g_vbh + vb) = h2;
    *(__nv_bfloat162*)(g_vbl + vb) = l2;
}

// ---------------- pad fills ----------------
__global__ void fill_pad2(const float* __restrict__ bias)
{
    int rid = blockIdx.x;
    int e = threadIdx.x * 2;
    if (rid < 6144) {
        int b = rid / 3072;
        int rem = rid - b * 3072;
        int pr = rem >> 9, l = rem & 511;
        const int tt[6] = {0, 0, 1, 0, 1, 2};
        const int ii[6] = {0, 1, 0, 2, 1, 0};
        int t = tt[pr], i = ii[pr];
        float x = bias[512 + e]     + g_teK[i * 512 + e];
        float y = bias[512 + e + 1] + g_teK[i * 512 + e + 1];
        __nv_bfloat162 h, lo2;
        split2(x, y, h, lo2);
        size_t o = ((size_t)((b * 8 + t) * 4 + i) * 512 + l) * 512 + e;
        *(__nv_bfloat162*)(g_kwh + o) = h;
        *(__nv_bfloat162*)(g_kwl + o) = lo2;
    } else {
        int rid2 = rid - 6144;
        int b = rid2 / 1536;
        int rem = rid2 - b * 1536;
        int fp = rem >> 9, l = rem & 511;
        __nv_bfloat162 h, lo2;
        split2(bias[1024 + e], bias[1024 + e + 1], h, lo2);
        size_t o = ((size_t)(b * 11 + fp) * 512 + l) * 512 + e;
        *(__nv_bfloat162*)(g_vph + o) = h;
        *(__nv_bfloat162*)(g_vpl + o) = lo2;
    }
}

// ---------------- teK: warp-per-output, lane-split K + shfl reduce ----------------
__global__ void compute_teK(const float* __restrict__ te, const float* __restrict__ W)
{
    int o = blockIdx.x * 8 + (threadIdx.x >> 5);   // 0..2047
    int lane = threadIdx.x & 31;
    int i = o >> 9, e = o & 511;
    const float4* wk = (const float4*)(W + (size_t)(512 + e) * 512) + lane * 4;
    const float4* tr = (const float4*)(te + i * 512) + lane * 4;
    float s = 0.f;
    #pragma unroll
    for (int k = 0; k < 4; k++) {
        float4 a = tr[k], b = wk[k];
        s += a.x * b.x + a.y * b.y + a.z * b.z + a.w * b.w;
    }
    #pragma unroll
    for (int d = 16; d > 0; d >>= 1) s += __shfl_xor_sync(0xffffffffu, s, d);
    if (lane == 0) g_teK[i * 512 + e] = s;
}

// ---------------- tensor-core flash attention, 3-stage cp.async pipeline ----------------
__global__ void __launch_bounds__(256) attn_mma()
{
    const int f = blockIdx.z, head = blockIdx.y;
    const int tid = threadIdx.x, w = tid >> 5, lane = tid & 31;
    const int b = f >> 3, t = f & 7;
    const int n32 = head * 32;
    const int qbase = blockIdx.x * 256 + w * 32;

    // [buf 0..2][arr: 0=Kh 1=Kl 2=Vh 3=Vl][32*40]
    __shared__ __align__(16) __nv_bfloat16 sKV[3][4][32 * 40];

    // ---- Q fragments loaded directly from gmem (m16n8k16 A layout) ----
    uint32_t Qh[2][2][4], Ql[2][2][4];
    {
        int r = lane >> 2, c = (lane & 3) * 2;
        #pragma unroll
        for (int mt = 0; mt < 2; mt++)
            #pragma unroll
            for (int kt = 0; kt < 2; kt++) {
                size_t base = (size_t)(f * 512 + qbase + mt * 16 + r) * 512 + n32 + kt * 16 + c;
                Qh[mt][kt][0] = *(const uint32_t*)(g_qwh + base);
                Qh[mt][kt][1] = *(const uint32_t*)(g_qwh + base + 8 * 512);
                Qh[mt][kt][2] = *(const uint32_t*)(g_qwh + base + 8);
                Qh[mt][kt][3] = *(const uint32_t*)(g_qwh + base + 8 * 512 + 8);
                Ql[mt][kt][0] = *(const uint32_t*)(g_qwl + base);
                Ql[mt][kt][1] = *(const uint32_t*)(g_qwl + base + 8 * 512);
                Ql[mt][kt][2] = *(const uint32_t*)(g_qwl + base + 8);
                Ql[mt][kt][3] = *(const uint32_t*)(g_qwl + base + 8 * 512 + 8);
            }
    }

    float O[2][4][4];
    float lsum[2][2] = {{0.f, 0.f}, {0.f, 0.f}};
    #pragma unroll
    for (int m = 0; m < 2; m++)
        #pragma unroll
        for (int n = 0; n < 4; n++)
            #pragma unroll
            for (int c = 0; c < 4; c++) O[m][n][c] = 0.f;

    // per-thread staging map: 2 cp.async of 16B each
    const int idx0 = tid * 2;
    const int arr0 = idx0 >> 7;
    const int r0s = (idx0 >> 2) & 31, seg0 = idx0 & 3;
    const int r1s = ((idx0 + 1) >> 2) & 31, seg1 = (idx0 + 1) & 3;

    auto stage = [&](int cc, int buf) {
        int slot = cc >> 4, lb = (cc & 15) << 5;
        size_t krow = (size_t)((b * 8 + t) * 4 + slot) * 512 + lb;
        size_t vrow = (size_t)(b * 11 + t + slot) * 512 + lb;
        const __nv_bfloat16* base =
            (arr0 == 0) ? g_kwh + (krow * 512 + n32) :
            (arr0 == 1) ? g_kwl + (krow * 512 + n32) :
            (arr0 == 2) ? g_vph + (vrow * 512 + n32) :
                          g_vpl + (vrow * 512 + n32);
        cp16(smem_u32(&sKV[buf][arr0][r0s * 40 + seg0 * 8]), base + (size_t)r0s * 512 + seg0 * 8);
        cp16(smem_u32(&sKV[buf][arr0][r1s * 40 + seg1 * 8]), base + (size_t)r1s * 512 + seg1 * 8);
        CP_COMMIT();
    };

    stage(0, 0);
    stage(1, 1);

    for (int cc = 0; cc < 64; cc++) {
        CP_WAIT1();
        __syncthreads();
        if (cc + 2 < 64) stage(cc + 2, (cc + 2) % 3); else CP_COMMIT();
        const int buf = cc % 3;

        // ---- S = Q @ K^T (3-pass split) ----
        float S[2][4][4];
        #pragma unroll
        for (int m = 0; m < 2; m++)
            #pragma unroll
            for (int n = 0; n < 4; n++)
                #pragma unroll
                for (int c = 0; c < 4; c++) S[m][n][c] = 0.f;

        #pragma unroll
        for (int kt = 0; kt < 2; kt++) {
            #pragma unroll
            for (int nt = 0; nt < 4; nt++) {
                int l = lane & 15;
                int ki = (nt * 8 + (l & 7)) * 40 + kt * 16 + (l >> 3) * 8;
                uint32_t kh0, kh1, kl0, kl1;
                ldsm_x2(kh0, kh1, smem_u32(&sKV[buf][0][ki]));
                ldsm_x2(kl0, kl1, smem_u32(&sKV[buf][1][ki]));
                #pragma unroll
                for (int m = 0; m < 2; m++) {
                    mma16816(S[m][nt], Qh[m][kt], kh0, kh1);
                    mma16816(S[m][nt], Qh[m][kt], kl0, kl1);
                    mma16816(S[m][nt], Ql[m][kt], kh0, kh1);
                }
            }
        }

        // ---- exp2 + lsum (q was pre-scaled by log2 e) ----
        #pragma unroll
        for (int m = 0; m < 2; m++)
            #pragma unroll
            for (int n = 0; n < 4; n++) {
                S[m][n][0] = exp2f(S[m][n][0]);
                S[m][n][1] = exp2f(S[m][n][1]);
                S[m][n][2] = exp2f(S[m][n][2]);
                S[m][n][3] = exp2f(S[m][n][3]);
                lsum[m][0] += S[m][n][0] + S[m][n][1];
                lsum[m][1] += S[m][n][2] + S[m][n][3];
            }

        // ---- O += P @ V (3-pass split) ----
        #pragma unroll
        for (int kt = 0; kt < 2; kt++) {
            uint32_t Ph[2][4], Pl[2][4];
            #pragma unroll
            for (int m = 0; m < 2; m++) {
                const float* s0 = S[m][2 * kt];
                const float* s1 = S[m][2 * kt + 1];
                Ph[m][0] = bfpack_hi(s0[0], s0[1]); Pl[m][0] = bfpack_lo(s0[0], s0[1]);
                Ph[m][1] = bfpack_hi(s0[2], s0[3]); Pl[m][1] = bfpack_lo(s0[2], s0[3]);
                Ph[m][2] = bfpack_hi(s1[0], s1[1]); Pl[m][2] = bfpack_lo(s1[0], s1[1]);
                Ph[m][3] = bfpack_hi(s1[2], s1[3]); Pl[m][3] = bfpack_lo(s1[2], s1[3]);
            }
            #pragma unroll
            for (int nt = 0; nt < 4; nt++) {
                int l = lane & 15;
                int vi = (kt * 16 + l) * 40 + nt * 8;
                uint32_t vh0, vh1, vl0, vl1;
                ldsm_x2t(vh0, vh1, smem_u32(&sKV[buf][2][vi]));
                ldsm_x2t(vl0, vl1, smem_u32(&sKV[buf][3][vi]));
                #pragma unroll
                for (int m = 0; m < 2; m++) {
                    mma16816(O[m][nt], Ph[m], vh0, vh1);
                    mma16816(O[m][nt], Ph[m], vl0, vl1);
                    mma16816(O[m][nt], Pl[m], vh0, vh1);
                }
            }
        }
    }

    // ---- epilogue ----
    float inv[2][2];
    #pragma unroll
    for (int m = 0; m < 2; m++)
        #pragma unroll
        for (int h = 0; h < 2; h++) {
            float s = lsum[m][h];
            s += __shfl_xor_sync(0xffffffffu, s, 1);
            s += __shfl_xor_sync(0xffffffffu, s, 2);
            inv[m][h] = 1.f / s;
        }
    #pragma unroll
    for (int m = 0; m < 2; m++) {
        int r0 = f * 512 + qbase + m * 16 + (lane >> 2);
        #pragma unroll
        for (int nt = 0; nt < 4; nt++) {
            int col = n32 + nt * 8 + (lane & 3) * 2;
            float a0 = O[m][nt][0] * inv[m][0], a1 = O[m][nt][1] * inv[m][0];
            float a2 = O[m][nt][2] * inv[m][1], a3 = O[m][nt][3] * inv[m][1];
            *(uint32_t*)(g_obh + (size_t)r0 * 512 + col)       = bfpack_hi(a0, a1);
            *(uint32_t*)(g_obl + (size_t)r0 * 512 + col)       = bfpack_lo(a0, a1);
            *(uint32_t*)(g_obh + (size_t)(r0 + 8) * 512 + col) = bfpack_hi(a2, a3);
            *(uint32_t*)(g_obl + (size_t)(r0 + 8) * 512 + col) = bfpack_lo(a2, a3);
        }
    }
}

// ---------------- launcher ----------------
extern "C" void kernel_launch(void* const* d_in, const int* in_sizes, int n_in,
                              void* d_out, int out_size)
{
    const float* hidden = (const float*)d_in[0];
    const float* W      = (const float*)d_in[1];
    const float* bias   = (const float*)d_in[2];
    const float* Wo     = (const float*)d_in[3];
    const float* bo     = (const float*)d_in[4];
    const float* te     = (const float*)d_in[5];
    float* out = (float*)d_out;

    float* p_qkv;
    __nv_bfloat16 *p_hh, *p_hl, *p_Wh, *p_Wl, *p_Woh, *p_Wol;
    __nv_bfloat16 *p_qbh, *p_qbl, *p_kbh, *p_kbl, *p_vbh, *p_vbl, *p_obh, *p_obl;
    cudaGetSymbolAddress((void**)&p_qkv, g_qkv);
    cudaGetSymbolAddress((void**)&p_hh,  g_hh);   cudaGetSymbolAddress((void**)&p_hl,  g_hl);
    cudaGetSymbolAddress((void**)&p_Wh,  g_Wh);   cudaGetSymbolAddress((void**)&p_Wl,  g_Wl);
    cudaGetSymbolAddress((void**)&p_Woh, g_Woh);  cudaGetSymbolAddress((void**)&p_Wol, g_Wol);
    cudaGetSymbolAddress((void**)&p_qbh, g_qbh);  cudaGetSymbolAddress((void**)&p_qbl, g_qbl);
    cudaGetSymbolAddress((void**)&p_kbh, g_kbh);  cudaGetSymbolAddress((void**)&p_kbl, g_kbl);
    cudaGetSymbolAddress((void**)&p_vbh, g_vbh);  cudaGetSymbolAddress((void**)&p_vbl, g_vbl);
    cudaGetSymbolAddress((void**)&p_obh, g_obh);  cudaGetSymbolAddress((void**)&p_obl, g_obl);

    cudaFuncSetAttribute(gemm_wmma, cudaFuncAttributeMaxDynamicSharedMemorySize, GEMM_SMEM);
    cudaFuncSetAttribute(gemm_small, cudaFuncAttributeMaxDynamicSharedMemorySize, GEMM_SMEM);

    // 0) split fp32 inputs into bf16 hi/lo (one launch)
    split_all<<<5120, 256>>>(hidden, W, Wo);

    // 1) teK = temporal_embed @ Wk^T
    compute_teK<<<256, 256>>>(te, W);

    // 2) qkv = hidden @ in_proj_W^T + b
    gemm_wmma<<<dim3(12, 64), 256, GEMM_SMEM>>>(p_hh, p_hl, p_Wh, p_Wl, bias, p_qkv, 1536);

    // 3) RoPE + stream reorder
    rope_reorder<<<8192, 256>>>(p_qkv);

    // 4) pad fills
    fill_pad2<<<6144 + 3072, 256>>>(bias);

    // 5) fused second projections
    gemm_small<<<dim3(4, 64, 3), 256, GEMM_SMEM>>>(p_qbh, p_qbl, p_kbh, p_kbl, p_vbh, p_vbl,
                                                   p_Wh, p_Wl, bias);

    // 6) sliding-window attention
    attn_mma<<<dim3(2, 16, 16), 256>>>();

    // 7) out = o @ Wo^T + bo
    gemm_wmma<<<dim3(4, 64), 256, GEMM_SMEM>>>(p_obh, p_obl, p_Woh, p_Wol, bo, out, 512);
}

// round 9
// speedup vs baseline: 3.1385x; 1.0050x over previous
#include <cuda_runtime.h>
#include <cuda_bf16.h>
#include <mma.h>
#include <math.h>
#include <cstdint>

using namespace nvcuda;

// ---------------- problem constants ----------------
// B=2, T=8, H=16, W=16, E=512, n_heads=16, d=32, S=4096, L2=512, WINDOW=4
// frames BT=16, padded frames per batch TPAD=11, K of all GEMMs = 512

// ---------------- device scratch ----------------
__device__ __align__(128) float g_teK[4 * 512];

__device__ __align__(128) __nv_bfloat16 g_hh [8192ull * 512], g_hl [8192ull * 512];
__device__ __align__(128) __nv_bfloat16 g_Wh [1536ull * 512], g_Wl [1536ull * 512];
__device__ __align__(128) __nv_bfloat16 g_Woh[ 512ull * 512], g_Wol[ 512ull * 512];
__device__ __align__(128) __nv_bfloat16 g_qbh[8192ull * 512], g_qbl[8192ull * 512];
__device__ __align__(128) __nv_bfloat16 g_kbh[8192ull * 512], g_kbl[8192ull * 512];
__device__ __align__(128) __nv_bfloat16 g_vbh[8192ull * 512], g_vbl[8192ull * 512];
__device__ __align__(128) __nv_bfloat16 g_obh[8192ull * 512], g_obl[8192ull * 512];

// attention operands, precomputed split
__device__ __align__(128) __nv_bfloat16 g_qwh[8192ull * 512], g_qwl[8192ull * 512];
__device__ __align__(128) __nv_bfloat16 g_kwh[2ull*8*4*512*512], g_kwl[2ull*8*4*512*512];
__device__ __align__(128) __nv_bfloat16 g_vph[2ull*11*512*512],  g_vpl[2ull*11*512*512];

// ---------------- helpers ----------------
__device__ __forceinline__ void split2(float x, float y,
                                       __nv_bfloat162& h, __nv_bfloat162& l) {
    __nv_bfloat16 hx = __float2bfloat16_rn(x);
    __nv_bfloat16 hy = __float2bfloat16_rn(y);
    h = __halves2bfloat162(hx, hy);
    l = __halves2bfloat162(__float2bfloat16_rn(x - __bfloat162float(hx)),
                           __float2bfloat16_rn(y - __bfloat162float(hy)));
}
__device__ __forceinline__ uint32_t bfpack_hi(float x, float y) {
    __nv_bfloat162 h = __floats2bfloat162_rn(x, y);
    return *(uint32_t*)&h;
}
__device__ __forceinline__ uint32_t bfpack_lo(float x, float y) {
    float rx = __bfloat162float(__float2bfloat16_rn(x));
    float ry = __bfloat162float(__float2bfloat16_rn(y));
    __nv_bfloat162 l = __floats2bfloat162_rn(x - rx, y - ry);
    return *(uint32_t*)&l;
}
__device__ __forceinline__ uint32_t smem_u32(const void* p) {
    uint32_t a;
    asm("{ .reg .u64 t; cvta.to.shared.u64 t, %1; cvt.u32.u64 %0, t; }" : "=r"(a) : "l"(p));
    return a;
}
__device__ __forceinline__ void ldsm_x2(uint32_t& r0, uint32_t& r1, uint32_t addr) {
    asm volatile("ldmatrix.sync.aligned.m8n8.x2.shared.b16 {%0,%1}, [%2];"
        : "=r"(r0), "=r"(r1) : "r"(addr));
}
__device__ __forceinline__ void ldsm_x2t(uint32_t& r0, uint32_t& r1, uint32_t addr) {
    asm volatile("ldmatrix.sync.aligned.m8n8.x2.trans.shared.b16 {%0,%1}, [%2];"
        : "=r"(r0), "=r"(r1) : "r"(addr));
}
__device__ __forceinline__ void mma16816(float* d, const uint32_t* a, uint32_t b0, uint32_t b1) {
    asm volatile("mma.sync.aligned.m16n8k16.row.col.f32.bf16.bf16.f32 "
        "{%0,%1,%2,%3}, {%4,%5,%6,%7}, {%8,%9}, {%0,%1,%2,%3};"
        : "+f"(d[0]), "+f"(d[1]), "+f"(d[2]), "+f"(d[3])
        : "r"(a[0]), "r"(a[1]), "r"(a[2]), "r"(a[3]), "r"(b0), "r"(b1));
}
__device__ __forceinline__ void cp16(uint32_t dst, const void* src) {
    asm volatile("cp.async.cg.shared.global [%0], [%1], 16;" :: "r"(dst), "l"(src));
}
#define CP_COMMIT() asm volatile("cp.async.commit_group;" ::: "memory")
#define CP_WAIT0()  asm volatile("cp.async.wait_group 0;" ::: "memory")
#define CP_WAIT1()  asm volatile("cp.async.wait_group 1;" ::: "memory")

// rope angle for (s, pair-index-within-head j)
__device__ __forceinline__ void rope_cs(int s, int j, float& cs, float& sn) {
    int fidx; float pos;
    if (s < 2048) { fidx = j; pos = (float)(s & 255); }
    else {
        int pp = (s - 2048) & 255;
        if (j < 8) { fidx = 2 * j;           pos = (float)(pp >> 4); }
        else       { fidx = 2 * (j - 8) + 1; pos = (float)(pp & 15); }
    }
    float freq = __powf(10000.0f, -(float)fidx * (1.0f / 16.0f));
    sincosf(pos * freq, &sn, &cs);
}

// ---------------- fused bf16 split of the 3 fp32 inputs ----------------
__global__ void split_all(const float* __restrict__ hidden, const float* __restrict__ W,
                          const float* __restrict__ Wo)
{
    int bid = blockIdx.x;
    const float* src;
    __nv_bfloat16 *hi, *lo;
    int rb;
    if (bid < 4096)      { src = hidden; hi = g_hh;  lo = g_hl;  rb = bid; }
    else if (bid < 4864) { src = W;      hi = g_Wh;  lo = g_Wl;  rb = bid - 4096; }
    else                 { src = Wo;     hi = g_Woh; lo = g_Wol; rb = bid - 4864; }
    size_t i = ((size_t)rb * 256 + threadIdx.x) * 4;
    float4 v = *(const float4*)(src + i);
    __nv_bfloat162 h0, l0, h1, l1;
    split2(v.x, v.y, h0, l0);
    split2(v.z, v.w, h1, l1);
    *(__nv_bfloat162*)(hi + i)     = h0;
    *(__nv_bfloat162*)(hi + i + 2) = h1;
    *(__nv_bfloat162*)(lo + i)     = l0;
    *(__nv_bfloat162*)(lo + i + 2) = l1;
}

// ---------------- cp.async double-buffered GEMM mainloop ----------------
#define GEMM_MAINLOOP(Ahi, Alo, Bhi, Blo)                                           \
    wmma::fragment<wmma::accumulator, 16, 16, 16, float> fc[4][2];                  \
    _Pragma("unroll") for (int i = 0; i < 4; i++)                                   \
        _Pragma("unroll") for (int j = 0; j < 2; j++) wmma::fill_fragment(fc[i][j], 0.f); \
    auto stage = [&](int st) {                                                      \
        int k0 = st * 32;                                                           \
        int bo = (st & 1) * 20480;                                                  \
        _Pragma("unroll") for (int i = 0; i < 8; i++) {                             \
            int c = tid + i * 256;                                                  \
            int arr = c >> 9, rem = c & 511, row = rem >> 2, seg = rem & 3;         \
            const __nv_bfloat16* src =                                              \
                (arr == 0) ? Ahi + (size_t)(m0 + row) * 512 + k0 + seg * 8 :        \
                (arr == 1) ? Alo + (size_t)(m0 + row) * 512 + k0 + seg * 8 :        \
                (arr == 2) ? Bhi + (size_t)(n0 + row) * 512 + k0 + seg * 8 :        \
                             Blo + (size_t)(n0 + row) * 512 + k0 + seg * 8;         \
            cp16(smem_u32(smp + bo + arr * 5120 + row * 40 + seg * 8), src);        \
        }                                                                           \
        CP_COMMIT();                                                                \
    };                                                                              \
    stage(0);                                                                       \
    for (int st = 0; st < 16; st++) {                                               \
        CP_WAIT0();                                                                 \
        __syncthreads();                                                            \
        if (st + 1 < 16) stage(st + 1);                                             \
        const __nv_bfloat16* sAh = smp + (st & 1) * 20480;                          \
        const __nv_bfloat16* sAl = sAh + 5120;                                      \
        const __nv_bfloat16* sBh = sAh + 10240;                                     \
        const __nv_bfloat16* sBl = sAh + 15360;                                     \
        _Pragma("unroll") for (int ks = 0; ks < 32; ks += 16) {                     \
            wmma::fragment<wmma::matrix_a, 16, 16, 16, __nv_bfloat16, wmma::row_major> fah[4], fal[4]; \
            wmma::fragment<wmma::matrix_b, 16, 16, 16, __nv_bfloat16, wmma::col_major> fbh[2], fbl[2]; \
            _Pragma("unroll") for (int i = 0; i < 4; i++) {                         \
                wmma::load_matrix_sync(fah[i], &sAh[(wm + i * 16) * 40 + ks], 40);  \
                wmma::load_matrix_sync(fal[i], &sAl[(wm + i * 16) * 40 + ks], 40);  \
            }                                                                       \
            _Pragma("unroll") for (int j = 0; j < 2; j++) {                         \
                wmma::load_matrix_sync(fbh[j], &sBh[(wn + j * 16) * 40 + ks], 40);  \
                wmma::load_matrix_sync(fbl[j], &sBl[(wn + j * 16) * 40 + ks], 40);  \
            }                                                                       \
            _Pragma("unroll") for (int i = 0; i < 4; i++)                           \
                _Pragma("unroll") for (int j = 0; j < 2; j++) {                     \
                    wmma::mma_sync(fc[i][j], fah[i], fbh[j], fc[i][j]);             \
                    wmma::mma_sync(fc[i][j], fah[i], fbl[j], fc[i][j]);             \
                    wmma::mma_sync(fc[i][j], fal[i], fbh[j], fc[i][j]);             \
                }                                                                   \
        }                                                                           \
        __syncthreads();                                                            \
    }

static constexpr int GEMM_SMEM = 2 * 4 * 5120 * 2;  // 81920 bytes

// ---------------- big qkv GEMM with fused RoPE + reorder + bf16-split epilogue ----------------
// C row gr = token (b*4096+s), col gn in [0,1536): z = gn>>9 selects q/k/v.
__global__ void __launch_bounds__(256, 2) gemm_rope(
    const __nv_bfloat16* __restrict__ Ahi, const __nv_bfloat16* __restrict__ Alo,
    const __nv_bfloat16* __restrict__ Bhi, const __nv_bfloat16* __restrict__ Blo,
    const float* __restrict__ bias)
{
    extern __shared__ __align__(16) __nv_bfloat16 smp[];
    const int tid = threadIdx.x, w = tid >> 5, lane = tid & 31;
    const int m0 = blockIdx.y * 128, n0 = blockIdx.x * 128;
    const int wm = (w >> 2) * 64, wn = (w & 3) * 32;

    GEMM_MAINLOOP(Ahi, Alo, Bhi, Blo)

    float* cst = reinterpret_cast<float*>(smp) + w * 256;
    const int er = lane >> 1, ec = (lane & 1) * 8;
    #pragma unroll
    for (int i = 0; i < 4; i++)
        #pragma unroll
        for (int j = 0; j < 2; j++) {
            wmma::store_matrix_sync(cst, fc[i][j], 16, wmma::mem_row_major);
            __syncwarp();
            int gr = m0 + wm + i * 16 + er;
            int gn = n0 + wn + j * 16 + ec;
            int b = gr >> 12, s = gr & 4095;
            float v[8];
            #pragma unroll
            for (int c = 0; c < 8; c++) v[c] = cst[er * 16 + ec + c] + bias[gn + c];

            int z = gn >> 9;   // block-uniform (128 | 512)
            if (z == 2) {
                // v: straight reshape, no rope
                int frame = b * 8 + (s >> 9), l = s & 511;
                size_t o = ((size_t)frame * 512 + l) * 512 + (gn & 511);
                #pragma unroll
                for (int c = 0; c < 8; c += 2) {
                    __nv_bfloat162 h2, l2;
                    split2(v[c], v[c + 1], h2, l2);
                    *(__nv_bfloat162*)(g_vbh + o + c) = h2;
                    *(__nv_bfloat162*)(g_vbl + o + c) = l2;
                }
            } else {
                // q or k: stream reorder + rope
                int frame, l;
                if (s < 2048) { frame = b * 8 + (s >> 8); l = s & 255; }
                else { int s2 = s - 2048; frame = b * 8 + (s2 >> 8); l = 256 + (s2 & 255); }
                size_t o = ((size_t)frame * 512 + l) * 512 + (gn & 511);
                __nv_bfloat16* hi = z ? g_kbh : g_qbh;
                __nv_bfloat16* lo = z ? g_kbl : g_qbl;
                #pragma unroll
                for (int c = 0; c < 8; c += 2) {
                    int pj = ((gn + c) >> 1) & 15;
                    float cs, sn;
                    rope_cs(s, pj, cs, sn);
                    float xr = v[c] * cs - v[c + 1] * sn;
                    float xi = v[c] * sn + v[c + 1] * cs;
                    __nv_bfloat162 h2, l2;
                    split2(xr, xi, h2, l2);
                    *(__nv_bfloat162*)(hi + o + c) = h2;
                    *(__nv_bfloat162*)(lo + o + c) = l2;
                }
            }
            __syncwarp();
        }
}

// ---------------- GEMM with fp32 output (out-proj) ----------------
__global__ void __launch_bounds__(256, 2) gemm_wmma(
    const __nv_bfloat16* __restrict__ Ahi, const __nv_bfloat16* __restrict__ Alo,
    const __nv_bfloat16* __restrict__ Bhi, const __nv_bfloat16* __restrict__ Blo,
    const float* __restrict__ bias, float* __restrict__ C, int N)
{
    extern __shared__ __align__(16) __nv_bfloat16 smp[];
    const int tid = threadIdx.x, w = tid >> 5, lane = tid & 31;
    const int m0 = blockIdx.y * 128, n0 = blockIdx.x * 128;
    const int wm = (w >> 2) * 64, wn = (w & 3) * 32;

    GEMM_MAINLOOP(Ahi, Alo, Bhi, Blo)

    float* cst = reinterpret_cast<float*>(smp) + w * 256;
    const int er = lane >> 1, ec = (lane & 1) * 8;
    #pragma unroll
    for (int i = 0; i < 4; i++)
        #pragma unroll
        for (int j = 0; j < 2; j++) {
            wmma::store_matrix_sync(cst, fc[i][j], 16, wmma::mem_row_major);
            __syncwarp();
            int gr = m0 + wm + i * 16 + er;
            int gn = n0 + wn + j * 16 + ec;
            float4 v0 = *(float4*)&cst[er * 16 + ec];
            float4 v1 = *(float4*)&cst[er * 16 + ec + 4];
            float4 b0 = *(const float4*)(bias + gn);
            float4 b1 = *(const float4*)(bias + gn + 4);
            v0.x += b0.x; v0.y += b0.y; v0.z += b0.z; v0.w += b0.w;
            v1.x += b1.x; v1.y += b1.y; v1.z += b1.z; v1.w += b1.w;
            float* crow = C + (size_t)gr * N + gn;
            *(float4*)crow = v0;
            *(float4*)(crow + 4) = v1;
            __syncwarp();
        }
}

// ---------------- fused second projections (z = 0:q, 1:k-window, 2:v-padded) ----------------
__global__ void __launch_bounds__(256, 2) gemm_small(
    const __nv_bfloat16* __restrict__ qAh, const __nv_bfloat16* __restrict__ qAl,
    const __nv_bfloat16* __restrict__ kAh, const __nv_bfloat16* __restrict__ kAl,
    const __nv_bfloat16* __restrict__ vAh, const __nv_bfloat16* __restrict__ vAl,
    const __nv_bfloat16* __restrict__ Wh,  const __nv_bfloat16* __restrict__ Wl,
    const float* __restrict__ bias_all)
{
    extern __shared__ __align__(16) __nv_bfloat16 smp[];
    const int tid = threadIdx.x, w = tid >> 5, lane = tid & 31;
    const int z = blockIdx.z;
    const int m0 = blockIdx.y * 128, n0 = blockIdx.x * 128;
    const int wm = (w >> 2) * 64, wn = (w & 3) * 32;

    const __nv_bfloat16* Ahi = (z == 0) ? qAh : (z == 1) ? kAh : vAh;
    const __nv_bfloat16* Alo = (z == 0) ? qAl : (z == 1) ? kAl : vAl;
    const __nv_bfloat16* Bhi = Wh + (size_t)z * 512 * 512;
    const __nv_bfloat16* Blo = Wl + (size_t)z * 512 * 512;
    const float* bias = bias_all + z * 512;

    GEMM_MAINLOOP(Ahi, Alo, Bhi, Blo)

    float* cst = reinterpret_cast<float*>(smp) + w * 256;
    const int er = lane >> 1, ec = (lane & 1) * 8;
    // q pre-scale folds 1/sqrt(d) AND log2(e) (attention uses exp2)
    const float scale = 0.17677669529663689f * 1.4426950408889634f;
    #pragma unroll
    for (int i = 0; i < 4; i++)
        #pragma unroll
        for (int j = 0; j < 2; j++) {
            wmma::store_matrix_sync(cst, fc[i][j], 16, wmma::mem_row_major);
            __syncwarp();
            int gr = m0 + wm + i * 16 + er;
            int gn = n0 + wn + j * 16 + ec;
            float v[8];
            #pragma unroll
            for (int c = 0; c < 8; c++) v[c] = cst[er * 16 + ec + c] + bias[gn + c];

            if (z == 0) {
                size_t o = (size_t)gr * 512 + gn;
                #pragma unroll
                for (int c = 0; c < 8; c += 2) {
                    __nv_bfloat162 h, l;
                    split2(v[c] * scale, v[c + 1] * scale, h, l);
                    *(__nv_bfloat162*)(g_qwh + o + c) = h;
                    *(__nv_bfloat162*)(g_qwl + o + c) = l;
                }
            } else if (z == 1) {
                int b = gr >> 12, f = (gr >> 9) & 7, l = gr & 511;
                #pragma unroll
                for (int ii = 0; ii < 4; ii++) {
                    int t = f + 3 - ii;
                    if ((unsigned)t < 8u) {
                        size_t o = ((size_t)((b * 8 + t) * 4 + ii) * 512 + l) * 512 + gn;
                        const float* tek = g_teK + ii * 512 + gn;
                        #pragma unroll
                        for (int c = 0; c < 8; c += 2) {
                            __nv_bfloat162 h, lo2;
                            split2(v[c] + tek[c], v[c + 1] + tek[c + 1], h, lo2);
                            *(__nv_bfloat162*)(g_kwh + o + c) = h;
                            *(__nv_bfloat162*)(g_kwl + o + c) = lo2;
                        }
                    }
                }
            } else {
                int out_r = gr + ((gr >> 12) + 1) * 1536;
                size_t o = (size_t)out_r * 512 + gn;
                #pragma unroll
                for (int c = 0; c < 8; c += 2) {
                    __nv_bfloat162 h, l;
                    split2(v[c], v[c + 1], h, l);
                    *(__nv_bfloat162*)(g_vph + o + c) = h;
                    *(__nv_bfloat162*)(g_vpl + o + c) = l;
                }
            }
            __syncwarp();
        }
}

// ---------------- pad fills ----------------
__global__ void fill_pad2(const float* __restrict__ bias)
{
    int rid = blockIdx.x;
    int e = threadIdx.x * 2;
    if (rid < 6144) {
        int b = rid / 3072;
        int rem = rid - b * 3072;
        int pr = rem >> 9, l = rem & 511;
        const int tt[6] = {0, 0, 1, 0, 1, 2};
        const int ii[6] = {0, 1, 0, 2, 1, 0};
        int t = tt[pr], i = ii[pr];
        float x = bias[512 + e]     + g_teK[i * 512 + e];
        float y = bias[512 + e + 1] + g_teK[i * 512 + e + 1];
        __nv_bfloat162 h, lo2;
        split2(x, y, h, lo2);
        size_t o = ((size_t)((b * 8 + t) * 4 + i) * 512 + l) * 512 + e;
        *(__nv_bfloat162*)(g_kwh + o) = h;
        *(__nv_bfloat162*)(g_kwl + o) = lo2;
    } else {
        int rid2 = rid - 6144;
        int b = rid2 / 1536;
        int rem = rid2 - b * 1536;
        int fp = rem >> 9, l = rem & 511;
        __nv_bfloat162 h, lo2;
        split2(bias[1024 + e], bias[1024 + e + 1], h, lo2);
        size_t o = ((size_t)(b * 11 + fp) * 512 + l) * 512 + e;
        *(__nv_bfloat162*)(g_vph + o) = h;
        *(__nv_bfloat162*)(g_vpl + o) = lo2;
    }
}

// ---------------- teK: warp-per-output ----------------
__global__ void compute_teK(const float* __restrict__ te, const float* __restrict__ W)
{
    int o = blockIdx.x * 8 + (threadIdx.x >> 5);
    int lane = threadIdx.x & 31;
    int i = o >> 9, e = o & 511;
    const float4* wk = (const float4*)(W + (size_t)(512 + e) * 512) + lane * 4;
    const float4* tr = (const float4*)(te + i * 512) + lane * 4;
    float s = 0.f;
    #pragma unroll
    for (int k = 0; k < 4; k++) {
        float4 a = tr[k], b = wk[k];
        s += a.x * b.x + a.y * b.y + a.z * b.z + a.w * b.w;
    }
    #pragma unroll
    for (int d = 16; d > 0; d >>= 1) s += __shfl_xor_sync(0xffffffffu, s, d);
    if (lane == 0) g_teK[i * 512 + e] = s;
}

// ---------------- tensor-core flash attention, 3-stage cp.async pipeline ----------------
// Full 3-pass split on BOTH QK^T and PV (the P_lo pass is required for rel_err<1e-3).
__global__ void __launch_bounds__(256) attn_mma()
{
    const int f = blockIdx.z, head = blockIdx.y;
    const int tid = threadIdx.x, w = tid >> 5, lane = tid & 31;
    const int b = f >> 3, t = f & 7;
    const int n32 = head * 32;
    const int qbase = blockIdx.x * 256 + w * 32;

    __shared__ __align__(16) __nv_bfloat16 sKV[3][4][32 * 40];

    uint32_t Qh[2][2][4], Ql[2][2][4];
    {
        int r = lane >> 2, c = (lane & 3) * 2;
        #pragma unroll
        for (int mt = 0; mt < 2; mt++)
            #pragma unroll
            for (int kt = 0; kt < 2; kt++) {
                size_t base = (size_t)(f * 512 + qbase + mt * 16 + r) * 512 + n32 + kt * 16 + c;
                Qh[mt][kt][0] = *(const uint32_t*)(g_qwh + base);
                Qh[mt][kt][1] = *(const uint32_t*)(g_qwh + base + 8 * 512);
                Qh[mt][kt][2] = *(const uint32_t*)(g_qwh + base + 8);
                Qh[mt][kt][3] = *(const uint32_t*)(g_qwh + base + 8 * 512 + 8);
                Ql[mt][kt][0] = *(const uint32_t*)(g_qwl + base);
                Ql[mt][kt][1] = *(const uint32_t*)(g_qwl + base + 8 * 512);
                Ql[mt][kt][2] = *(const uint32_t*)(g_qwl + base + 8);
                Ql[mt][kt][3] = *(const uint32_t*)(g_qwl + base + 8 * 512 + 8);
            }
    }

    float O[2][4][4];
    float lsum[2][2] = {{0.f, 0.f}, {0.f, 0.f}};
    #pragma unroll
    for (int m = 0; m < 2; m++)
        #pragma unroll
        for (int n = 0; n < 4; n++)
            #pragma unroll
            for (int c = 0; c < 4; c++) O[m][n][c] = 0.f;

    const int idx0 = tid * 2;
    const int arr0 = idx0 >> 7;
    const int r0s = (idx0 >> 2) & 31, seg0 = idx0 & 3;
    const int r1s = ((idx0 + 1) >> 2) & 31, seg1 = (idx0 + 1) & 3;

    auto stage = [&](int cc, int buf) {
        int slot = cc >> 4, lb = (cc & 15) << 5;
        size_t krow = (size_t)((b * 8 + t) * 4 + slot) * 512 + lb;
        size_t vrow = (size_t)(b * 11 + t + slot) * 512 + lb;
        const __nv_bfloat16* base =
            (arr0 == 0) ? g_kwh + (krow * 512 + n32) :
            (arr0 == 1) ? g_kwl + (krow * 512 + n32) :
            (arr0 == 2) ? g_vph + (vrow * 512 + n32) :
                          g_vpl + (vrow * 512 + n32);
        cp16(smem_u32(&sKV[buf][arr0][r0s * 40 + seg0 * 8]), base + (size_t)r0s * 512 + seg0 * 8);
        cp16(smem_u32(&sKV[buf][arr0][r1s * 40 + seg1 * 8]), base + (size_t)r1s * 512 + seg1 * 8);
        CP_COMMIT();
    };

    stage(0, 0);
    stage(1, 1);

    for (int cc = 0; cc < 64; cc++) {
        CP_WAIT1();
        __syncthreads();
        if (cc + 2 < 64) stage(cc + 2, (cc + 2) % 3); else CP_COMMIT();
        const int buf = cc % 3;

        // ---- S = Q @ K^T (3-pass split) ----
        float S[2][4][4];
        #pragma unroll
        for (int m = 0; m < 2; m++)
            #pragma unroll
            for (int n = 0; n < 4; n++)
                #pragma unroll
                for (int c = 0; c < 4; c++) S[m][n][c] = 0.f;

        #pragma unroll
        for (int kt = 0; kt < 2; kt++) {
            #pragma unroll
            for (int nt = 0; nt < 4; nt++) {
                int l = lane & 15;
                int ki = (nt * 8 + (l & 7)) * 40 + kt * 16 + (l >> 3) * 8;
                uint32_t kh0, kh1, kl0, kl1;
                ldsm_x2(kh0, kh1, smem_u32(&sKV[buf][0][ki]));
                ldsm_x2(kl0, kl1, smem_u32(&sKV[buf][1][ki]));
                #pragma unroll
                for (int m = 0; m < 2; m++) {
                    mma16816(S[m][nt], Qh[m][kt], kh0, kh1);
                    mma16816(S[m][nt], Qh[m][kt], kl0, kl1);
                    mma16816(S[m][nt], Ql[m][kt], kh0, kh1);
                }
            }
        }

        // ---- exp2 + lsum ----
        #pragma unroll
        for (int m = 0; m < 2; m++)
            #pragma unroll
            for (int n = 0; n < 4; n++) {
                S[m][n][0] = exp2f(S[m][n][0]);
                S[m][n][1] = exp2f(S[m][n][1]);
                S[m][n][2] = exp2f(S[m][n][2]);
                S[m][n][3] = exp2f(S[m][n][3]);
                lsum[m][0] += S[m][n][0] + S[m][n][1];
                lsum[m][1] += S[m][n][2] + S[m][n][3];
            }

        // ---- O += P @ V (3-pass split) ----
        #pragma unroll
        for (int kt = 0; kt < 2; kt++) {
            uint32_t Ph[2][4], Pl[2][4];
            #pragma unroll
            for (int m = 0; m < 2; m++) {
                const float* s0 = S[m][2 * kt];
                const float* s1 = S[m][2 * kt + 1];
                Ph[m][0] = bfpack_hi(s0[0], s0[1]); Pl[m][0] = bfpack_lo(s0[0], s0[1]);
                Ph[m][1] = bfpack_hi(s0[2], s0[3]); Pl[m][1] = bfpack_lo(s0[2], s0[3]);
                Ph[m][2] = bfpack_hi(s1[0], s1[1]); Pl[m][2] = bfpack_lo(s1[0], s1[1]);
                Ph[m][3] = bfpack_hi(s1[2], s1[3]); Pl[m][3] = bfpack_lo(s1[2], s1[3]);
            }
            #pragma unroll
            for (int nt = 0; nt < 4; nt++) {
                int l = lane & 15;
                int vi = (kt * 16 + l) * 40 + nt * 8;
                uint32_t vh0, vh1, vl0, vl1;
                ldsm_x2t(vh0, vh1, smem_u32(&sKV[buf][2][vi]));
                ldsm_x2t(vl0, vl1, smem_u32(&sKV[buf][3][vi]));
                #pragma unroll
                for (int m = 0; m < 2; m++) {
                    mma16816(O[m][nt], Ph[m], vh0, vh1);
                    mma16816(O[m][nt], Ph[m], vl0, vl1);
                    mma16816(O[m][nt], Pl[m], vh0, vh1);
                }
            }
        }
    }

    // ---- epilogue ----
    float inv[2][2];
    #pragma unroll
    for (int m = 0; m < 2; m++)
        #pragma unroll
        for (int h = 0; h < 2; h++) {
            float s = lsum[m][h];
            s += __shfl_xor_sync(0xffffffffu, s, 1);
            s += __shfl_xor_sync(0xffffffffu, s, 2);
            inv[m][h] = 1.f / s;
        }
    #pragma unroll
    for (int m = 0; m < 2; m++) {
        int r0 = f * 512 + qbase + m * 16 + (lane >> 2);
        #pragma unroll
        for (int nt = 0; nt < 4; nt++) {
            int col = n32 + nt * 8 + (lane & 3) * 2;
            float a0 = O[m][nt][0] * inv[m][0], a1 = O[m][nt][1] * inv[m][0];
            float a2 = O[m][nt][2] * inv[m][1], a3 = O[m][nt][3] * inv[m][1];
            __nv_bfloat162 h0, l0, h1, l1;
            split2(a0, a1, h0, l0);
            split2(a2, a3, h1, l1);
            *(__nv_bfloat162*)(g_obh + (size_t)r0 * 512 + col)       = h0;
            *(__nv_bfloat162*)(g_obl + (size_t)r0 * 512 + col)       = l0;
            *(__nv_bfloat162*)(g_obh + (size_t)(r0 + 8) * 512 + col) = h1;
            *(__nv_bfloat162*)(g_obl + (size_t)(r0 + 8) * 512 + col) = l1;
        }
    }
}

// ---------------- launcher ----------------
extern "C" void kernel_launch(void* const* d_in, const int* in_sizes, int n_in,
                              void* d_out, int out_size)
{
    const float* hidden = (const float*)d_in[0];
    const float* W      = (const float*)d_in[1];
    const float* bias   = (const float*)d_in[2];
    const float* Wo     = (const float*)d_in[3];
    const float* bo     = (const float*)d_in[4];
    const float* te     = (const float*)d_in[5];
    float* out = (float*)d_out;

    __nv_bfloat16 *p_hh, *p_hl, *p_Wh, *p_Wl, *p_Woh, *p_Wol;
    __nv_bfloat16 *p_qbh, *p_qbl, *p_kbh, *p_kbl, *p_vbh, *p_vbl, *p_obh, *p_obl;
    cudaGetSymbolAddress((void**)&p_hh,  g_hh);   cudaGetSymbolAddress((void**)&p_hl,  g_hl);
    cudaGetSymbolAddress((void**)&p_Wh,  g_Wh);   cudaGetSymbolAddress((void**)&p_Wl,  g_Wl);
    cudaGetSymbolAddress((void**)&p_Woh, g_Woh);  cudaGetSymbolAddress((void**)&p_Wol, g_Wol);
    cudaGetSymbolAddress((void**)&p_qbh, g_qbh);  cudaGetSymbolAddress((void**)&p_qbl, g_qbl);
    cudaGetSymbolAddress((void**)&p_kbh, g_kbh);  cudaGetSymbolAddress((void**)&p_kbl, g_kbl);
    cudaGetSymbolAddress((void**)&p_vbh, g_vbh);  cudaGetSymbolAddress((void**)&p_vbl, g_vbl);
    cudaGetSymbolAddress((void**)&p_obh, g_obh);  cudaGetSymbolAddress((void**)&p_obl, g_obl);

    cudaFuncSetAttribute(gemm_rope,  cudaFuncAttributeMaxDynamicSharedMemorySize, GEMM_SMEM);
    cudaFuncSetAttribute(gemm_wmma,  cudaFuncAttributeMaxDynamicSharedMemorySize, GEMM_SMEM);
    cudaFuncSetAttribute(gemm_small, cudaFuncAttributeMaxDynamicSharedMemorySize, GEMM_SMEM);

    // 0) split fp32 inputs into bf16 hi/lo
    split_all<<<5120, 256>>>(hidden, W, Wo);

    // 1) teK = temporal_embed @ Wk^T
    compute_teK<<<256, 256>>>(te, W);

    // 2) qkv GEMM with fused RoPE + reorder + split epilogue
    gemm_rope<<<dim3(12, 64), 256, GEMM_SMEM>>>(p_hh, p_hl, p_Wh, p_Wl, bias);

    // 3) pad fills
    fill_pad2<<<6144 + 3072, 256>>>(bias);

    // 4) fused second projections
    gemm_small<<<dim3(4, 64, 3), 256, GEMM_SMEM>>>(p_qbh, p_qbl, p_kbh, p_kbl, p_vbh, p_vbl,
                                                   p_Wh, p_Wl, bias);

    // 5) sliding-window attention
    attn_mma<<<dim3(2, 16, 16), 256>>>();

    // 6) out = o @ Wo^T + bo
    gemm_wmma<<<dim3(4, 64), 256, GEMM_SMEM>>>(p_obh, p_obl, p_Woh, p_Wol, bo, out, 512);
}